// round 3
// baseline (speedup 1.0000x reference)
#include <cuda_runtime.h>
#include <math.h>
#include <float.h>

#define S_ASP 4
#define C_CL  1024
#define NKEYS 131072
#define DK    128
#define DA    2048
#define M_TOP 32
#define K_MAX 64
#define BB    64
#define NPC   128              /* NKEYS/C_CL */
#define M_CAND 4096            /* M_TOP*NPC */
#define EPSF  1e-8f

__device__ float g_part[32 * S_ASP * DK * BB];
__device__ float g_qwT [S_ASP * DK * BB];       /* w_s * l2norm(q): [s][k][b] */
__device__ float g_cscore[BB * C_CL];
__device__ int   g_topc [BB * M_TOP];
__device__ float g_sif  [(size_t)BB * NKEYS];   /* 32 MB */
__device__ float g_cmax [BB * 32];
__device__ float g_csum [BB * 32];
__device__ float g_rmax [BB];
__device__ float g_rsum [BB];

/* K1: query GEMM partials. grid 256 = s(4) x ac(32) x kh(2), 128 thr */
__global__ void __launch_bounds__(128) k_qpart(const float* __restrict__ WQ,
                                               const float* __restrict__ z) {
    int bx = blockIdx.x, s = bx >> 6, ac = (bx >> 1) & 31, kh = bx & 1;
    int a0 = ac * 64;
    __shared__ float sW[64 * 65], sZ[64 * 65];
    int tid = threadIdx.x;
    for (int idx = tid; idx < 64 * 64; idx += 128) {
        int kl = idx >> 6, aa = idx & 63;
        sW[kl * 65 + aa] = WQ[(size_t)s * DK * DA + (kh * 64 + kl) * DA + a0 + aa];
    }
    for (int idx = tid; idx < 64 * 64; idx += 128) {
        int b = idx >> 6, aa = idx & 63;
        sZ[b * 65 + aa] = z[b * DA + a0 + aa];
    }
    __syncthreads();
    int krow = tid >> 3, bcol = tid & 7;
    float acc[4][8];
#pragma unroll
    for (int i = 0; i < 4; i++)
#pragma unroll
        for (int j = 0; j < 8; j++) acc[i][j] = 0.f;
    for (int aa = 0; aa < 64; aa++) {
        float qk[4], zb[8];
#pragma unroll
        for (int i = 0; i < 4; i++) qk[i] = sW[(krow * 4 + i) * 65 + aa];
#pragma unroll
        for (int j = 0; j < 8; j++) zb[j] = sZ[(bcol * 8 + j) * 65 + aa];
#pragma unroll
        for (int i = 0; i < 4; i++)
#pragma unroll
            for (int j = 0; j < 8; j++) acc[i][j] = fmaf(qk[i], zb[j], acc[i][j]);
    }
#pragma unroll
    for (int i = 0; i < 4; i++)
#pragma unroll
        for (int j = 0; j < 8; j++)
            g_part[((ac * S_ASP + s) * DK + kh * 64 + krow * 4 + i) * BB + bcol * 8 + j] = acc[i][j];
}

/* K2: combine, l2norm, fold softmax(aspect_weights). grid 256 = s*64+b, 128 thr */
__global__ void __launch_bounds__(128) k_qcombine(const float* __restrict__ aw) {
    int s = blockIdx.x >> 6, b = blockIdx.x & 63, k = threadIdx.x;
    float q = 0.f;
    for (int ac = 0; ac < 32; ac++) q += g_part[((ac * S_ASP + s) * DK + k) * BB + b];
    __shared__ float red[DK];
    red[k] = q * q; __syncthreads();
    for (int off = 64; off > 0; off >>= 1) {
        if (k < off) red[k] += red[k + off];
        __syncthreads();
    }
    float rinv = 1.f / (sqrtf(red[0]) + EPSF);
    float a0 = aw[0], a1 = aw[1], a2 = aw[2], a3 = aw[3];
    float mx = fmaxf(fmaxf(a0, a1), fmaxf(a2, a3));
    float e0 = expf(a0 - mx), e1 = expf(a1 - mx), e2 = expf(a2 - mx), e3 = expf(a3 - mx);
    float ws = (s == 0 ? e0 : s == 1 ? e1 : s == 2 ? e2 : e3) / (e0 + e1 + e2 + e3);
    g_qwT[(s * DK + k) * BB + b] = ws * q * rinv;
}

/* K3: centroid scores. grid 256 (4 centroids each), 256 thr */
__global__ void __launch_bounds__(256) k_centroid(const float* __restrict__ cent) {
    int c0 = blockIdx.x * 4, tid = threadIdx.x;
    __shared__ float sc[4][S_ASP][DK];
    __shared__ float srn[4][S_ASP];
    for (int idx = tid; idx < 4 * S_ASP * DK; idx += 256) {
        int r = idx >> 7, k = idx & 127, c = r >> 2, s = r & 3;
        sc[c][s][k] = cent[((size_t)s * C_CL + c0 + c) * DK + k];
    }
    __syncthreads();
    if (tid < 16) {
        int c = tid >> 2, s = tid & 3;
        float ss = 0.f;
        for (int k = 0; k < DK; k++) { float v = sc[c][s][k]; ss += v * v; }
        srn[c][s] = 1.f / (sqrtf(ss) + EPSF);
    }
    __syncthreads();
    int c = tid >> 6, b = tid & 63;
    float acc = 0.f;
    for (int s = 0; s < S_ASP; s++) {
        float p = 0.f;
#pragma unroll 4
        for (int k = 0; k < DK; k++) p = fmaf(g_qwT[(s * DK + k) * BB + b], sc[c][s][k], p);
        acc = fmaf(p, srn[c][s], acc);
    }
    g_cscore[b * C_CL + c0 + c] = acc;
}

/* K4: top-32 clusters, ties -> lower index. grid 64, 256 thr */
__global__ void __launch_bounds__(256) k_topc() {
    int b = blockIdx.x, tid = threadIdx.x;
    __shared__ float sc[C_CL];
    __shared__ float bv[256];
    __shared__ int   bi[256];
    for (int i = tid; i < C_CL; i += 256) sc[i] = g_cscore[b * C_CL + i];
    __syncthreads();
    for (int r = 0; r < M_TOP; r++) {
        float best = -FLT_MAX; int bidx = 0x7fffffff;
        for (int i = tid; i < C_CL; i += 256) {
            float v = sc[i];
            if (v > best) { best = v; bidx = i; }
        }
        bv[tid] = best; bi[tid] = bidx; __syncthreads();
        for (int off = 128; off > 0; off >>= 1) {
            if (tid < off) {
                float v2 = bv[tid + off]; int i2 = bi[tid + off];
                if (v2 > bv[tid] || (v2 == bv[tid] && i2 < bi[tid])) { bv[tid] = v2; bi[tid] = i2; }
            }
            __syncthreads();
        }
        if (tid == 0) { g_topc[b * M_TOP + r] = bi[0]; sc[bi[0]] = -FLT_MAX; }
        __syncthreads();
    }
}

/* K5: dense pass. grid 4096 (32 keys), 128 thr, 4x4 reg tile.
   smem = 48KB exactly: sqw[k][b] 32KB + skeyT[k][n-swz] 16KB */
__global__ void __launch_bounds__(128) k_dense(const float* __restrict__ keys) {
    __shared__ float sqw[DK * BB];
    __shared__ float skeyT[DK * 32];   /* (n,k) at k*32 + (n ^ (k&28)) */
    int tid = threadIdx.x;
    int brow = tid >> 3, ncol = tid & 7;
    int n0 = blockIdx.x * 32;
    int w = tid >> 5, l = tid & 31;
    int nn = w * 8 + (l >> 2), qq = l & 3;

    float acc[4][4];
#pragma unroll
    for (int i = 0; i < 4; i++)
#pragma unroll
        for (int j = 0; j < 4; j++) acc[i][j] = 0.f;

    for (int s = 0; s < S_ASP; s++) {
        __syncthreads();
        {   /* qw tile */
            const float4* src = (const float4*)(g_qwT + s * DK * BB);
            float4* dst = (float4*)sqw;
            for (int i = tid; i < DK * BB / 4; i += 128) dst[i] = src[i];
        }
        {   /* key tile, transposed + swizzled */
            const float* kb = keys + ((size_t)s * NKEYS + n0) * DK;
#pragma unroll 4
            for (int r = 0; r < 32; r++)
                skeyT[tid * 32 + (r ^ (tid & 28))] = kb[r * DK + tid];
        }
        __syncthreads();
        {   /* per-key inverse norm, scale keys in place */
            float ss = 0.f;
#pragma unroll 4
            for (int i = 0; i < 32; i++) {
                int k = qq * 32 + i;
                float v = skeyT[k * 32 + (nn ^ (k & 28))];
                ss = fmaf(v, v, ss);
            }
            ss += __shfl_xor_sync(0xffffffffu, ss, 1);
            ss += __shfl_xor_sync(0xffffffffu, ss, 2);
            float rn = 1.f / (sqrtf(ss) + EPSF);
#pragma unroll 4
            for (int i = 0; i < 32; i++) {
                int k = qq * 32 + i;
                skeyT[k * 32 + (nn ^ (k & 28))] *= rn;
            }
        }
        __syncthreads();
        /* main dot: 16 FMA per k per thread */
#pragma unroll 2
        for (int k = 0; k < DK; k++) {
            float4 qv = *(const float4*)(sqw + k * BB + (brow << 2));
            float4 kv = *(const float4*)(skeyT + k * 32 + ((ncol << 2) ^ (k & 28)));
#pragma unroll
            for (int i = 0; i < 4; i++) {
                float qi = i == 0 ? qv.x : i == 1 ? qv.y : i == 2 ? qv.z : qv.w;
                acc[i][0] = fmaf(qi, kv.x, acc[i][0]);
                acc[i][1] = fmaf(qi, kv.y, acc[i][1]);
                acc[i][2] = fmaf(qi, kv.z, acc[i][2]);
                acc[i][3] = fmaf(qi, kv.w, acc[i][3]);
            }
        }
    }
#pragma unroll
    for (int i = 0; i < 4; i++) {
        int b = (brow << 2) + i;
        float4 v = make_float4(acc[i][0], acc[i][1], acc[i][2], acc[i][3]);
        *(float4*)(g_sif + (size_t)b * NKEYS + n0 + (ncol << 2)) = v;
    }
}

/* K6: per-chunk online softmax stats. grid 2048 = b*32+c, 256 thr, 16 elem/thr */
__global__ void __launch_bounds__(256) k_smax_part(const float* __restrict__ tau_unused) {
    int b = blockIdx.x >> 5, c = blockIdx.x & 31, tid = threadIdx.x;
    const float* row = g_sif + (size_t)b * NKEYS + c * 4096;
    float v[16];
    float m = -FLT_MAX;
#pragma unroll
    for (int i = 0; i < 16; i++) { v[i] = row[tid + 256 * i]; m = fmaxf(m, v[i]); }
    __shared__ float sm[256];
    sm[tid] = m; __syncthreads();
    for (int off = 128; off > 0; off >>= 1) {
        if (tid < off) sm[tid] = fmaxf(sm[tid], sm[tid + off]);
        __syncthreads();
    }
    float bm = sm[0]; __syncthreads();
    float sum = 0.f;
#pragma unroll
    for (int i = 0; i < 16; i++) sum += __expf(v[i] - bm);
    sm[tid] = sum; __syncthreads();
    for (int off = 128; off > 0; off >>= 1) {
        if (tid < off) sm[tid] += sm[tid + off];
        __syncthreads();
    }
    if (tid == 0) { g_cmax[b * 32 + c] = bm; g_csum[b * 32 + c] = sm[0]; }
}

/* K7: combine chunk stats. grid 64, 32 thr */
__global__ void __launch_bounds__(32) k_smax_comb() {
    int b = blockIdx.x, t = threadIdx.x;
    float m = g_cmax[b * 32 + t], s = g_csum[b * 32 + t];
    float M = m;
    for (int off = 16; off > 0; off >>= 1) M = fmaxf(M, __shfl_xor_sync(0xffffffffu, M, off));
    float part = s * __expf(m - M);
    for (int off = 16; off > 0; off >>= 1) part += __shfl_xor_sync(0xffffffffu, part, off);
    if (t == 0) { g_rmax[b] = M; g_rsum[b] = part; }
}

/* K8: write soft_full. grid 2048, 256 thr */
__global__ void __launch_bounds__(256) k_smax_write(float* __restrict__ out) {
    int b = blockIdx.x >> 5, c = blockIdx.x & 31, tid = threadIdx.x;
    const float* row = g_sif + (size_t)b * NKEYS + c * 4096;
    float* orow = out + 2 * BB * K_MAX + (size_t)b * NKEYS + c * 4096;
    float M = g_rmax[b], inv = 1.f / g_rsum[b];
#pragma unroll 4
    for (int i = 0; i < 16; i++) {
        int idx = tid + 256 * i;
        orow[idx] = __expf(row[idx] - M) * inv;
    }
}

/* K9: refine (gather from s_i_full) + top-64 + alphas. grid 64, 256 thr */
__global__ void __launch_bounds__(256) k_refine(const float* __restrict__ taup,
                                                const float* __restrict__ lamp,
                                                const int* __restrict__ warmp,
                                                float* __restrict__ out) {
    int b = blockIdx.x, tid = threadIdx.x;
    __shared__ float raw[M_CAND];
    __shared__ float bv[256];
    __shared__ int   bi[256];
    __shared__ float vals[K_MAX];
    __shared__ int   gids[K_MAX];
    __shared__ float sD;
    float tau = taup[0], lam = lamp[0];
    int warm = warmp[0];

    float lsum = 0.f;
    for (int i = tid; i < M_CAND; i += 256) {
        int cl = g_topc[b * M_TOP + (i >> 7)];
        int gidx = cl * NPC + (i & 127);
        float si = g_sif[(size_t)b * NKEYS + gidx];
        float r;
        if (warm) r = si;
        else {
            float g = 1.f / (1.f + expf(-lam * (si - tau)));
            r = g * expf(si);
        }
        raw[i] = r;
        lsum += r;
    }
    bv[tid] = lsum; __syncthreads();
    for (int off = 128; off > 0; off >>= 1) {
        if (tid < off) bv[tid] += bv[tid + off];
        __syncthreads();
    }
    if (tid == 0) sD = bv[0] + EPSF;
    __syncthreads();
    if (!warm) {
        float invD = 1.f / sD;
        for (int i = tid; i < M_CAND; i += 256) raw[i] *= invD;
    }
    __syncthreads();

    for (int r = 0; r < K_MAX; r++) {
        float best = -FLT_MAX; int bidx = 0x7fffffff;
        for (int i = tid; i < M_CAND; i += 256) {
            float v = raw[i];
            if (v > best) { best = v; bidx = i; }
        }
        bv[tid] = best; bi[tid] = bidx; __syncthreads();
        for (int off = 128; off > 0; off >>= 1) {
            if (tid < off) {
                float v2 = bv[tid + off]; int i2 = bi[tid + off];
                if (v2 > bv[tid] || (v2 == bv[tid] && i2 < bi[tid])) { bv[tid] = v2; bi[tid] = i2; }
            }
            __syncthreads();
        }
        if (tid == 0) {
            int li = bi[0];
            vals[r] = bv[0];
            gids[r] = g_topc[b * M_TOP + (li >> 7)] * NPC + (li & 127);
            raw[li] = -FLT_MAX;
        }
        __syncthreads();
    }

    if (tid == 0) {
        float alphas[K_MAX];
        if (warm) {
            float m = -FLT_MAX;
            for (int r = 0; r < K_MAX; r++) m = fmaxf(m, vals[r]);
            float s = 0.f;
            for (int r = 0; r < K_MAX; r++) { alphas[r] = expf(vals[r] - m); s += alphas[r]; }
            float inv = 1.f / s;
            for (int r = 0; r < K_MAX; r++) alphas[r] *= inv;
        } else {
            float s = 0.f;
            for (int r = 0; r < K_MAX; r++) s += vals[r];
            float inv = 1.f / (s + EPSF);
            for (int r = 0; r < K_MAX; r++) alphas[r] = vals[r] * inv;
        }
        for (int r = 0; r < K_MAX; r++) {
            out[b * K_MAX + r] = alphas[r];
            out[BB * K_MAX + b * K_MAX + r] = (float)gids[r];
        }
    }
}

extern "C" void kernel_launch(void* const* d_in, const int* in_sizes, int n_in,
                              void* d_out, int out_size) {
    const float* z    = (const float*)d_in[0];
    const float* keys = (const float*)d_in[1];
    const float* WQ   = (const float*)d_in[2];
    const float* aw   = (const float*)d_in[3];
    const float* tau  = (const float*)d_in[4];
    const float* cent = (const float*)d_in[5];
    const float* lam  = (const float*)d_in[6];
    const int*   warm = (const int*)d_in[7];
    float* out = (float*)d_out;

    k_qpart<<<256, 128>>>(WQ, z);
    k_qcombine<<<256, 128>>>(aw);
    k_centroid<<<256, 256>>>(cent);
    k_topc<<<64, 256>>>();
    k_dense<<<4096, 128>>>(keys);
    k_smax_part<<<2048, 256>>>(tau);
    k_smax_comb<<<64, 32>>>();
    k_smax_write<<<2048, 256>>>(out);
    k_refine<<<64, 256>>>(tau, lam, warm, out);
}

// round 4
// speedup vs baseline: 1.3014x; 1.3014x over previous
#include <cuda_runtime.h>
#include <math.h>
#include <float.h>

#define S_ASP 4
#define C_CL  1024
#define NKEYS 131072
#define DK    128
#define DA    2048
#define M_TOP 32
#define K_MAX 64
#define BB    64
#define NPC   128
#define M_CAND 4096
#define EPSF  1e-8f
#define DN    128            /* keys per dense block */

__device__ float g_part[32 * S_ASP * DK * BB];
__device__ float g_qwT [S_ASP * DK * BB];       /* w_s * l2norm(q): [s][k][b] */
__device__ float g_cscore[BB * C_CL];
__device__ int   g_topc [BB * M_TOP];
__device__ float g_sif  [(size_t)BB * NKEYS];   /* 32 MB */
__device__ float g_cmax [BB * 32];
__device__ float g_csum [BB * 32];
__device__ float g_rmax [BB];
__device__ float g_rsum [BB];

/* K1: query GEMM partials. grid 256 = s(4) x ac(32) x kh(2), 128 thr */
__global__ void __launch_bounds__(128) k_qpart(const float* __restrict__ WQ,
                                               const float* __restrict__ z) {
    int bx = blockIdx.x, s = bx >> 6, ac = (bx >> 1) & 31, kh = bx & 1;
    int a0 = ac * 64;
    __shared__ float sW[64 * 65], sZ[64 * 65];
    int tid = threadIdx.x;
    for (int idx = tid; idx < 64 * 64; idx += 128) {
        int kl = idx >> 6, aa = idx & 63;
        sW[kl * 65 + aa] = WQ[(size_t)s * DK * DA + (kh * 64 + kl) * DA + a0 + aa];
    }
    for (int idx = tid; idx < 64 * 64; idx += 128) {
        int b = idx >> 6, aa = idx & 63;
        sZ[b * 65 + aa] = z[b * DA + a0 + aa];
    }
    __syncthreads();
    int krow = tid >> 3, bcol = tid & 7;
    float acc[4][8];
#pragma unroll
    for (int i = 0; i < 4; i++)
#pragma unroll
        for (int j = 0; j < 8; j++) acc[i][j] = 0.f;
    for (int aa = 0; aa < 64; aa++) {
        float qk[4], zb[8];
#pragma unroll
        for (int i = 0; i < 4; i++) qk[i] = sW[(krow * 4 + i) * 65 + aa];
#pragma unroll
        for (int j = 0; j < 8; j++) zb[j] = sZ[(bcol * 8 + j) * 65 + aa];
#pragma unroll
        for (int i = 0; i < 4; i++)
#pragma unroll
            for (int j = 0; j < 8; j++) acc[i][j] = fmaf(qk[i], zb[j], acc[i][j]);
    }
#pragma unroll
    for (int i = 0; i < 4; i++)
#pragma unroll
        for (int j = 0; j < 8; j++)
            g_part[((ac * S_ASP + s) * DK + kh * 64 + krow * 4 + i) * BB + bcol * 8 + j] = acc[i][j];
}

/* K2: combine, l2norm, fold softmax(aspect_weights). grid 256 = s*64+b, 128 thr */
__global__ void __launch_bounds__(128) k_qcombine(const float* __restrict__ aw) {
    int s = blockIdx.x >> 6, b = blockIdx.x & 63, k = threadIdx.x;
    float q = 0.f;
    for (int ac = 0; ac < 32; ac++) q += g_part[((ac * S_ASP + s) * DK + k) * BB + b];
    __shared__ float red[DK];
    red[k] = q * q; __syncthreads();
    for (int off = 64; off > 0; off >>= 1) {
        if (k < off) red[k] += red[k + off];
        __syncthreads();
    }
    float rinv = 1.f / (sqrtf(red[0]) + EPSF);
    float a0 = aw[0], a1 = aw[1], a2 = aw[2], a3 = aw[3];
    float mx = fmaxf(fmaxf(a0, a1), fmaxf(a2, a3));
    float e0 = expf(a0 - mx), e1 = expf(a1 - mx), e2 = expf(a2 - mx), e3 = expf(a3 - mx);
    float ws = (s == 0 ? e0 : s == 1 ? e1 : s == 2 ? e2 : e3) / (e0 + e1 + e2 + e3);
    g_qwT[(s * DK + k) * BB + b] = ws * q * rinv;
}

/* K3: centroid scores. grid 256 (4 centroids each), 256 thr */
__global__ void __launch_bounds__(256) k_centroid(const float* __restrict__ cent) {
    int c0 = blockIdx.x * 4, tid = threadIdx.x;
    __shared__ float sc[4][S_ASP][DK];
    __shared__ float srn[4][S_ASP];
    for (int idx = tid; idx < 4 * S_ASP * DK; idx += 256) {
        int r = idx >> 7, k = idx & 127, c = r >> 2, s = r & 3;
        sc[c][s][k] = cent[((size_t)s * C_CL + c0 + c) * DK + k];
    }
    __syncthreads();
    if (tid < 16) {
        int c = tid >> 2, s = tid & 3;
        float ss = 0.f;
        for (int k = 0; k < DK; k++) { float v = sc[c][s][k]; ss += v * v; }
        srn[c][s] = 1.f / (sqrtf(ss) + EPSF);
    }
    __syncthreads();
    int c = tid >> 6, b = tid & 63;
    float acc = 0.f;
    for (int s = 0; s < S_ASP; s++) {
        float p = 0.f;
#pragma unroll 4
        for (int k = 0; k < DK; k++) p = fmaf(g_qwT[(s * DK + k) * BB + b], sc[c][s][k], p);
        acc = fmaf(p, srn[c][s], acc);
    }
    g_cscore[b * C_CL + c0 + c] = acc;
}

/* K4: top-32 of 1024, one warp per b. Cached local max; only winner rescans. */
__global__ void __launch_bounds__(32) k_topc() {
    int b = blockIdx.x, lane = threadIdx.x;
    __shared__ float sv[C_CL];           /* sv[j*32+lane] = cscore[b][j*32+lane] */
    for (int j = 0; j < 32; j++) sv[j * 32 + lane] = g_cscore[b * C_CL + j * 32 + lane];
    __syncwarp();
    float lv = -FLT_MAX; int lj = 0;
#pragma unroll
    for (int j = 0; j < 32; j++) {
        float v = sv[j * 32 + lane];
        if (v > lv) { lv = v; lj = j; }
    }
    for (int r = 0; r < M_TOP; r++) {
        float bv = lv; int bidx = lj * 32 + lane;
#pragma unroll
        for (int off = 16; off > 0; off >>= 1) {
            float ov = __shfl_xor_sync(0xffffffffu, bv, off);
            int   oi = __shfl_xor_sync(0xffffffffu, bidx, off);
            if (ov > bv || (ov == bv && oi < bidx)) { bv = ov; bidx = oi; }
        }
        if (lane == 0) g_topc[b * M_TOP + r] = bidx;
        if ((bidx & 31) == lane) {       /* owner: remove + rescan */
            sv[(bidx >> 5) * 32 + lane] = -FLT_MAX;
            lv = -FLT_MAX; lj = 0;
#pragma unroll
            for (int j = 0; j < 32; j++) {
                float v = sv[j * 32 + lane];
                if (v > lv) { lv = v; lj = j; }
            }
        }
        __syncwarp();
    }
}

/* K5: dense pass. grid 1024 (128 keys/block), 128 thr, 8x8 reg tile.
   dynamic smem 96KB: sqw[k][b] 32KB + skey[k][n-swz] 64KB */
__global__ void __launch_bounds__(128) k_dense(const float* __restrict__ keys) {
    extern __shared__ float sm[];
    float* sqw  = sm;             /* DK*BB   */
    float* skey = sm + DK * BB;   /* DK*DN: (k,n) at k*DN + (n ^ (k&28)) */
    int tid = threadIdx.x;
    int brow = tid >> 4;          /* 0..7  -> b0 = brow*8 */
    int ncol = tid & 15;          /* 0..15 -> n_local = ncol*8 */
    int n0 = blockIdx.x * DN;

    float acc[8][8];
#pragma unroll
    for (int i = 0; i < 8; i++)
#pragma unroll
        for (int j = 0; j < 8; j++) acc[i][j] = 0.f;

    for (int s = 0; s < S_ASP; s++) {
        __syncthreads();
        {   /* qw tile */
            const float4* src = (const float4*)(g_qwT + s * DK * BB);
            float4* dst = (float4*)sqw;
            for (int i = tid; i < DK * BB / 4; i += 128) dst[i] = src[i];
        }
        {   /* key tile, transposed + swizzled; thread = k index */
            const float* kb = keys + ((size_t)s * NKEYS + n0) * DK;
#pragma unroll 8
            for (int r = 0; r < DN; r++)
                skey[tid * DN + (r ^ (tid & 28))] = kb[r * DK + tid];
        }
        __syncthreads();
        {   /* normalize key n = tid in place */
            float ss = 0.f;
#pragma unroll 8
            for (int k = 0; k < DK; k++) {
                float v = skey[k * DN + (tid ^ (k & 28))];
                ss = fmaf(v, v, ss);
            }
            float rn = 1.f / (sqrtf(ss) + EPSF);
#pragma unroll 8
            for (int k = 0; k < DK; k++)
                skey[k * DN + (tid ^ (k & 28))] *= rn;
        }
        __syncthreads();
#pragma unroll 4
        for (int k = 0; k < DK; k++) {
            const float* qrow = sqw + k * BB + (brow << 3);
            float4 q0 = *(const float4*)(qrow);
            float4 q1 = *(const float4*)(qrow + 4);
            int a_lo = ((ncol << 3) ^ (k & 28));
            float4 kv0 = *(const float4*)(skey + k * DN + a_lo);
            float4 kv1 = *(const float4*)(skey + k * DN + (a_lo ^ 4));
            float qv[8] = {q0.x, q0.y, q0.z, q0.w, q1.x, q1.y, q1.z, q1.w};
            float kv[8] = {kv0.x, kv0.y, kv0.z, kv0.w, kv1.x, kv1.y, kv1.z, kv1.w};
#pragma unroll
            for (int i = 0; i < 8; i++)
#pragma unroll
                for (int j = 0; j < 8; j++)
                    acc[i][j] = fmaf(qv[i], kv[j], acc[i][j]);
        }
    }
#pragma unroll
    for (int i = 0; i < 8; i++) {
        float* dst = g_sif + (size_t)((brow << 3) + i) * NKEYS + n0 + (ncol << 3);
        *(float4*)dst       = make_float4(acc[i][0], acc[i][1], acc[i][2], acc[i][3]);
        *(float4*)(dst + 4) = make_float4(acc[i][4], acc[i][5], acc[i][6], acc[i][7]);
    }
}

/* K6: per-chunk softmax stats. grid 2048 = b*32+c, 256 thr, float4 */
__global__ void __launch_bounds__(256) k_smax_part() {
    int b = blockIdx.x >> 5, c = blockIdx.x & 31, tid = threadIdx.x;
    const float4* row = (const float4*)(g_sif + (size_t)b * NKEYS + c * 4096);
    float4 v[4];
    float m = -FLT_MAX;
#pragma unroll
    for (int i = 0; i < 4; i++) {
        v[i] = row[tid + 256 * i];
        m = fmaxf(m, fmaxf(fmaxf(v[i].x, v[i].y), fmaxf(v[i].z, v[i].w)));
    }
    __shared__ float smem[256];
    smem[tid] = m; __syncthreads();
    for (int off = 128; off > 0; off >>= 1) {
        if (tid < off) smem[tid] = fmaxf(smem[tid], smem[tid + off]);
        __syncthreads();
    }
    float bm = smem[0]; __syncthreads();
    float sum = 0.f;
#pragma unroll
    for (int i = 0; i < 4; i++)
        sum += __expf(v[i].x - bm) + __expf(v[i].y - bm) + __expf(v[i].z - bm) + __expf(v[i].w - bm);
    smem[tid] = sum; __syncthreads();
    for (int off = 128; off > 0; off >>= 1) {
        if (tid < off) smem[tid] += smem[tid + off];
        __syncthreads();
    }
    if (tid == 0) { g_cmax[b * 32 + c] = bm; g_csum[b * 32 + c] = smem[0]; }
}

/* K7: combine chunk stats. grid 64, 32 thr */
__global__ void __launch_bounds__(32) k_smax_comb() {
    int b = blockIdx.x, t = threadIdx.x;
    float m = g_cmax[b * 32 + t], s = g_csum[b * 32 + t];
    float M = m;
    for (int off = 16; off > 0; off >>= 1) M = fmaxf(M, __shfl_xor_sync(0xffffffffu, M, off));
    float part = s * __expf(m - M);
    for (int off = 16; off > 0; off >>= 1) part += __shfl_xor_sync(0xffffffffu, part, off);
    if (t == 0) { g_rmax[b] = M; g_rsum[b] = part; }
}

/* K8: write soft_full. grid 2048, 256 thr, float4 */
__global__ void __launch_bounds__(256) k_smax_write(float* __restrict__ out) {
    int b = blockIdx.x >> 5, c = blockIdx.x & 31, tid = threadIdx.x;
    const float4* row = (const float4*)(g_sif + (size_t)b * NKEYS + c * 4096);
    float4* orow = (float4*)(out + 2 * BB * K_MAX + (size_t)b * NKEYS + c * 4096);
    float M = g_rmax[b], inv = 1.f / g_rsum[b];
#pragma unroll
    for (int i = 0; i < 4; i++) {
        float4 v = row[tid + 256 * i];
        orow[tid + 256 * i] = make_float4(__expf(v.x - M) * inv, __expf(v.y - M) * inv,
                                          __expf(v.z - M) * inv, __expf(v.w - M) * inv);
    }
}

/* K9: refine + top-64 + alphas. grid 64, 256 thr. Cached local max per thread. */
__global__ void __launch_bounds__(256) k_refine(const float* __restrict__ taup,
                                                const float* __restrict__ lamp,
                                                const int* __restrict__ warmp,
                                                float* __restrict__ out) {
    int b = blockIdx.x, tid = threadIdx.x;
    int wid = tid >> 5, lane = tid & 31;
    __shared__ float raw[M_CAND];
    __shared__ float bvw[256];
    __shared__ float wv[8]; __shared__ int wi[8];
    __shared__ float win_v; __shared__ int win_i;
    __shared__ float vals[K_MAX];
    __shared__ int   gids[K_MAX];
    __shared__ float sD;
    float tau = taup[0], lam = lamp[0];
    int warm = warmp[0];

    float lsum = 0.f;
    for (int r = 0; r < 16; r++) {
        int i = tid + 256 * r;
        int cl = g_topc[b * M_TOP + (i >> 7)];
        float si = g_sif[(size_t)b * NKEYS + cl * NPC + (i & 127)];
        float v;
        if (warm) v = si;
        else {
            float g = 1.f / (1.f + expf(-lam * (si - tau)));
            v = g * expf(si);
        }
        raw[i] = v;
        lsum += v;
    }
    bvw[tid] = lsum; __syncthreads();
    for (int off = 128; off > 0; off >>= 1) {
        if (tid < off) bvw[tid] += bvw[tid + off];
        __syncthreads();
    }
    if (tid == 0) sD = bvw[0] + EPSF;
    __syncthreads();
    if (!warm) {
        float invD = 1.f / sD;
        for (int r = 0; r < 16; r++) raw[tid + 256 * r] *= invD;
    }
    __syncthreads();

    /* cached local max over i = tid + 256*r (ascending i keeps lowest idx on tie) */
    float lv = -FLT_MAX; int li = tid;
    for (int r = 0; r < 16; r++) {
        int i = tid + 256 * r;
        float v = raw[i];
        if (v > lv) { lv = v; li = i; }
    }
    for (int rr = 0; rr < K_MAX; rr++) {
        float bv = lv; int bidx = li;
#pragma unroll
        for (int off = 16; off > 0; off >>= 1) {
            float ov = __shfl_xor_sync(0xffffffffu, bv, off);
            int   oi = __shfl_xor_sync(0xffffffffu, bidx, off);
            if (ov > bv || (ov == bv && oi < bidx)) { bv = ov; bidx = oi; }
        }
        if (lane == 0) { wv[wid] = bv; wi[wid] = bidx; }
        __syncthreads();
        if (tid == 0) {
            float gbv = wv[0]; int gbi = wi[0];
            for (int w = 1; w < 8; w++) {
                if (wv[w] > gbv || (wv[w] == gbv && wi[w] < gbi)) { gbv = wv[w]; gbi = wi[w]; }
            }
            win_v = gbv; win_i = gbi;
            vals[rr] = gbv;
            gids[rr] = g_topc[b * M_TOP + (gbi >> 7)] * NPC + (gbi & 127);
        }
        __syncthreads();
        if ((win_i & 255) == tid) {   /* owner removes + rescans its 16 */
            raw[win_i] = -FLT_MAX;
            lv = -FLT_MAX; li = tid;
            for (int r = 0; r < 16; r++) {
                int i = tid + 256 * r;
                float v = raw[i];
                if (v > lv) { lv = v; li = i; }
            }
        }
        __syncthreads();
    }

    if (tid == 0) {
        float alphas[K_MAX];
        if (warm) {
            float m = -FLT_MAX;
            for (int r = 0; r < K_MAX; r++) m = fmaxf(m, vals[r]);
            float ssum = 0.f;
            for (int r = 0; r < K_MAX; r++) { alphas[r] = expf(vals[r] - m); ssum += alphas[r]; }
            float inv = 1.f / ssum;
            for (int r = 0; r < K_MAX; r++) alphas[r] *= inv;
        } else {
            float ssum = 0.f;
            for (int r = 0; r < K_MAX; r++) ssum += vals[r];
            float inv = 1.f / (ssum + EPSF);
            for (int r = 0; r < K_MAX; r++) alphas[r] = vals[r] * inv;
        }
        for (int r = 0; r < K_MAX; r++) {
            out[b * K_MAX + r] = alphas[r];
            out[BB * K_MAX + b * K_MAX + r] = (float)gids[r];
        }
    }
}

extern "C" void kernel_launch(void* const* d_in, const int* in_sizes, int n_in,
                              void* d_out, int out_size) {
    const float* z    = (const float*)d_in[0];
    const float* keys = (const float*)d_in[1];
    const float* WQ   = (const float*)d_in[2];
    const float* aw   = (const float*)d_in[3];
    const float* tau  = (const float*)d_in[4];
    const float* cent = (const float*)d_in[5];
    const float* lam  = (const float*)d_in[6];
    const int*   warm = (const int*)d_in[7];
    float* out = (float*)d_out;

    static const size_t dense_smem = (size_t)(DK * BB + DK * DN) * sizeof(float); /* 96KB */
    cudaFuncSetAttribute(k_dense, cudaFuncAttributeMaxDynamicSharedMemorySize, (int)dense_smem);

    k_qpart<<<256, 128>>>(WQ, z);
    k_qcombine<<<256, 128>>>(aw);
    k_centroid<<<256, 256>>>(cent);
    k_topc<<<64, 32>>>();
    k_dense<<<NKEYS / DN, 128, dense_smem>>>(keys);
    k_smax_part<<<2048, 256>>>();
    k_smax_comb<<<64, 32>>>();
    k_smax_write<<<2048, 256>>>(out);
    k_refine<<<64, 256>>>(tau, lam, warm, out);
}

// round 5
// speedup vs baseline: 1.3882x; 1.0667x over previous
#include <cuda_runtime.h>
#include <math.h>
#include <float.h>

#define S_ASP 4
#define C_CL  1024
#define NKEYS 131072
#define DK    128
#define DA    2048
#define M_TOP 32
#define K_MAX 64
#define BB    64
#define NPC   128
#define M_CAND 4096
#define EPSF  1e-8f
#define DN    128            /* keys per dense block */

__device__ float g_part[32 * S_ASP * DK * BB];
__device__ float g_qwT [S_ASP * DK * BB];       /* w_s * l2norm(q): [s][k][b] */
__device__ float g_cscore[BB * C_CL];
__device__ int   g_topc [BB * M_TOP];
__device__ float g_sif  [(size_t)BB * NKEYS];   /* 32 MB */
__device__ float g_cmax [BB * 32];
__device__ float g_csum [BB * 32];
__device__ float g_rmax [BB];
__device__ float g_rsum [BB];

/* ---- f32x2 helpers ---- */
__device__ __forceinline__ unsigned long long pk2(float a, float b) {
    unsigned long long r;
    asm("mov.b64 %0, {%1, %2};" : "=l"(r) : "r"(__float_as_uint(a)), "r"(__float_as_uint(b)));
    return r;
}
__device__ __forceinline__ void fma2(unsigned long long& d, unsigned long long a,
                                     unsigned long long b) {
    asm("fma.rn.f32x2 %0, %1, %2, %3;" : "=l"(d) : "l"(a), "l"(b), "l"(d));
}
__device__ __forceinline__ void upk2(unsigned long long v, float& lo, float& hi) {
    unsigned int l, h;
    asm("mov.b64 {%0, %1}, %2;" : "=r"(l), "=r"(h) : "l"(v));
    lo = __uint_as_float(l); hi = __uint_as_float(h);
}

/* K1: query GEMM partials. grid 256 = s(4) x ac(32) x kh(2), 128 thr */
__global__ void __launch_bounds__(128) k_qpart(const float* __restrict__ WQ,
                                               const float* __restrict__ z) {
    int bx = blockIdx.x, s = bx >> 6, ac = (bx >> 1) & 31, kh = bx & 1;
    int a0 = ac * 64;
    __shared__ float sW[64 * 65], sZ[64 * 65];
    int tid = threadIdx.x;
    for (int idx = tid; idx < 64 * 64; idx += 128) {
        int kl = idx >> 6, aa = idx & 63;
        sW[kl * 65 + aa] = WQ[(size_t)s * DK * DA + (kh * 64 + kl) * DA + a0 + aa];
    }
    for (int idx = tid; idx < 64 * 64; idx += 128) {
        int b = idx >> 6, aa = idx & 63;
        sZ[b * 65 + aa] = z[b * DA + a0 + aa];
    }
    __syncthreads();
    int krow = tid >> 3, bcol = tid & 7;
    float acc[4][8];
#pragma unroll
    for (int i = 0; i < 4; i++)
#pragma unroll
        for (int j = 0; j < 8; j++) acc[i][j] = 0.f;
    for (int aa = 0; aa < 64; aa++) {
        float qk[4], zb[8];
#pragma unroll
        for (int i = 0; i < 4; i++) qk[i] = sW[(krow * 4 + i) * 65 + aa];
#pragma unroll
        for (int j = 0; j < 8; j++) zb[j] = sZ[(bcol * 8 + j) * 65 + aa];
#pragma unroll
        for (int i = 0; i < 4; i++)
#pragma unroll
            for (int j = 0; j < 8; j++) acc[i][j] = fmaf(qk[i], zb[j], acc[i][j]);
    }
#pragma unroll
    for (int i = 0; i < 4; i++)
#pragma unroll
        for (int j = 0; j < 8; j++)
            g_part[((ac * S_ASP + s) * DK + kh * 64 + krow * 4 + i) * BB + bcol * 8 + j] = acc[i][j];
}

/* K2: combine, l2norm, fold softmax(aspect_weights). grid 256 = s*64+b, 128 thr */
__global__ void __launch_bounds__(128) k_qcombine(const float* __restrict__ aw) {
    int s = blockIdx.x >> 6, b = blockIdx.x & 63, k = threadIdx.x;
    float q = 0.f;
    for (int ac = 0; ac < 32; ac++) q += g_part[((ac * S_ASP + s) * DK + k) * BB + b];
    __shared__ float red[DK];
    red[k] = q * q; __syncthreads();
    for (int off = 64; off > 0; off >>= 1) {
        if (k < off) red[k] += red[k + off];
        __syncthreads();
    }
    float rinv = 1.f / (sqrtf(red[0]) + EPSF);
    float a0 = aw[0], a1 = aw[1], a2 = aw[2], a3 = aw[3];
    float mx = fmaxf(fmaxf(a0, a1), fmaxf(a2, a3));
    float e0 = expf(a0 - mx), e1 = expf(a1 - mx), e2 = expf(a2 - mx), e3 = expf(a3 - mx);
    float ws = (s == 0 ? e0 : s == 1 ? e1 : s == 2 ? e2 : e3) / (e0 + e1 + e2 + e3);
    g_qwT[(s * DK + k) * BB + b] = ws * q * rinv;
}

/* K3: centroid scores. grid 256 (4 centroids each), 256 thr */
__global__ void __launch_bounds__(256) k_centroid(const float* __restrict__ cent) {
    int c0 = blockIdx.x * 4, tid = threadIdx.x;
    __shared__ float sc[4][S_ASP][DK];
    __shared__ float srn[4][S_ASP];
    for (int idx = tid; idx < 4 * S_ASP * DK; idx += 256) {
        int r = idx >> 7, k = idx & 127, c = r >> 2, s = r & 3;
        sc[c][s][k] = cent[((size_t)s * C_CL + c0 + c) * DK + k];
    }
    __syncthreads();
    if (tid < 16) {
        int c = tid >> 2, s = tid & 3;
        float ss = 0.f;
        for (int k = 0; k < DK; k++) { float v = sc[c][s][k]; ss += v * v; }
        srn[c][s] = 1.f / (sqrtf(ss) + EPSF);
    }
    __syncthreads();
    int c = tid >> 6, b = tid & 63;
    float acc = 0.f;
    for (int s = 0; s < S_ASP; s++) {
        float p = 0.f;
#pragma unroll 4
        for (int k = 0; k < DK; k++) p = fmaf(g_qwT[(s * DK + k) * BB + b], sc[c][s][k], p);
        acc = fmaf(p, srn[c][s], acc);
    }
    g_cscore[b * C_CL + c0 + c] = acc;
}

/* K4: top-32 of 1024 via full bitonic sort of packed (score,idx) keys.
   grid 64, 512 thr. Key ascending == score descending, idx ascending on ties. */
__global__ void __launch_bounds__(512) k_topc() {
    int b = blockIdx.x, tid = threadIdx.x;
    __shared__ unsigned long long key[C_CL];
#pragma unroll
    for (int r = 0; r < 2; r++) {
        int i = tid + 512 * r;
        float v = g_cscore[b * C_CL + i];
        unsigned int u = __float_as_uint(v);
        u ^= (u & 0x80000000u) ? 0xFFFFFFFFu : 0x80000000u;   /* ascending == value ascending */
        unsigned int su = ~u;                                  /* ascending == value descending */
        key[i] = ((unsigned long long)su << 32) | (unsigned int)i;
    }
    __syncthreads();
    for (int size = 2; size <= C_CL; size <<= 1) {
        for (int stride = size >> 1; stride > 0; stride >>= 1) {
            int i = ((tid & ~(stride - 1)) << 1) | (tid & (stride - 1));
            int j = i + stride;
            bool up = ((i & size) == 0);
            unsigned long long a = key[i], c = key[j];
            bool sw = up ? (a > c) : (a < c);
            if (sw) { key[i] = c; key[j] = a; }
            __syncthreads();
        }
    }
    if (tid < M_TOP) g_topc[b * M_TOP + tid] = (int)(key[tid] & 0xFFFFFFFFu);
}

/* K5: dense pass, f32x2. grid 1024 (128 keys/block), 128 thr, 8x8 reg tile.
   dynamic smem 96KB: sqw[k][b] 32KB + skey[k][n-swz] 64KB */
__global__ void __launch_bounds__(128) k_dense(const float* __restrict__ keys) {
    extern __shared__ float sm[];
    float* sqw  = sm;             /* DK*BB */
    float* skey = sm + DK * BB;   /* DK*DN: (k,n) at k*DN + (n ^ (k&28)) */
    int tid = threadIdx.x;
    int brow = tid >> 4;          /* 0..7  -> b0 = brow*8 */
    int ncol = tid & 15;          /* 0..15 -> n_local = ncol*8 */
    int n0 = blockIdx.x * DN;

    unsigned long long accp[8][4];
#pragma unroll
    for (int i = 0; i < 8; i++)
#pragma unroll
        for (int j = 0; j < 4; j++) accp[i][j] = 0ull;

    for (int s = 0; s < S_ASP; s++) {
        __syncthreads();
        {   /* qw tile */
            const float4* src = (const float4*)(g_qwT + s * DK * BB);
            float4* dst = (float4*)sqw;
            for (int i = tid; i < DK * BB / 4; i += 128) dst[i] = src[i];
        }
        {   /* key tile, transposed + swizzled; thread = k index */
            const float* kb = keys + ((size_t)s * NKEYS + n0) * DK;
#pragma unroll 8
            for (int r = 0; r < DN; r++)
                skey[tid * DN + (r ^ (tid & 28))] = kb[r * DK + tid];
        }
        __syncthreads();
        {   /* normalize key n = tid in place */
            float ss = 0.f;
#pragma unroll 8
            for (int k = 0; k < DK; k++) {
                float v = skey[k * DN + (tid ^ (k & 28))];
                ss = fmaf(v, v, ss);
            }
            float rn = 1.f / (sqrtf(ss) + EPSF);
#pragma unroll 8
            for (int k = 0; k < DK; k++)
                skey[k * DN + (tid ^ (k & 28))] *= rn;
        }
        __syncthreads();
#pragma unroll 4
        for (int k = 0; k < DK; k++) {
            const float* qrow = sqw + k * BB + (brow << 3);
            float4 q0 = *(const float4*)(qrow);
            float4 q1 = *(const float4*)(qrow + 4);
            int a_lo = ((ncol << 3) ^ (k & 28));
            float4 kv0 = *(const float4*)(skey + k * DN + a_lo);
            float4 kv1 = *(const float4*)(skey + k * DN + (a_lo ^ 4));
            unsigned long long kp0 = pk2(kv0.x, kv0.y);
            unsigned long long kp1 = pk2(kv0.z, kv0.w);
            unsigned long long kp2 = pk2(kv1.x, kv1.y);
            unsigned long long kp3 = pk2(kv1.z, kv1.w);
            float qv[8] = {q0.x, q0.y, q0.z, q0.w, q1.x, q1.y, q1.z, q1.w};
#pragma unroll
            for (int i = 0; i < 8; i++) {
                unsigned long long qd = pk2(qv[i], qv[i]);
                fma2(accp[i][0], qd, kp0);
                fma2(accp[i][1], qd, kp1);
                fma2(accp[i][2], qd, kp2);
                fma2(accp[i][3], qd, kp3);
            }
        }
    }
#pragma unroll
    for (int i = 0; i < 8; i++) {
        float a0, a1, a2, a3, a4, a5, a6, a7;
        upk2(accp[i][0], a0, a1);
        upk2(accp[i][1], a2, a3);
        upk2(accp[i][2], a4, a5);
        upk2(accp[i][3], a6, a7);
        float* dst = g_sif + (size_t)((brow << 3) + i) * NKEYS + n0 + (ncol << 3);
        *(float4*)dst       = make_float4(a0, a1, a2, a3);
        *(float4*)(dst + 4) = make_float4(a4, a5, a6, a7);
    }
}

/* K6: per-chunk softmax stats. grid 2048 = b*32+c, 256 thr, float4 */
__global__ void __launch_bounds__(256) k_smax_part() {
    int b = blockIdx.x >> 5, c = blockIdx.x & 31, tid = threadIdx.x;
    const float4* row = (const float4*)(g_sif + (size_t)b * NKEYS + c * 4096);
    float4 v[4];
    float m = -FLT_MAX;
#pragma unroll
    for (int i = 0; i < 4; i++) {
        v[i] = row[tid + 256 * i];
        m = fmaxf(m, fmaxf(fmaxf(v[i].x, v[i].y), fmaxf(v[i].z, v[i].w)));
    }
    __shared__ float smem[256];
    smem[tid] = m; __syncthreads();
    for (int off = 128; off > 0; off >>= 1) {
        if (tid < off) smem[tid] = fmaxf(smem[tid], smem[tid + off]);
        __syncthreads();
    }
    float bm = smem[0]; __syncthreads();
    float sum = 0.f;
#pragma unroll
    for (int i = 0; i < 4; i++)
        sum += __expf(v[i].x - bm) + __expf(v[i].y - bm) + __expf(v[i].z - bm) + __expf(v[i].w - bm);
    smem[tid] = sum; __syncthreads();
    for (int off = 128; off > 0; off >>= 1) {
        if (tid < off) smem[tid] += smem[tid + off];
        __syncthreads();
    }
    if (tid == 0) { g_cmax[b * 32 + c] = bm; g_csum[b * 32 + c] = smem[0]; }
}

/* K7: combine chunk stats. grid 64, 32 thr */
__global__ void __launch_bounds__(32) k_smax_comb() {
    int b = blockIdx.x, t = threadIdx.x;
    float m = g_cmax[b * 32 + t], s = g_csum[b * 32 + t];
    float M = m;
    for (int off = 16; off > 0; off >>= 1) M = fmaxf(M, __shfl_xor_sync(0xffffffffu, M, off));
    float part = s * __expf(m - M);
    for (int off = 16; off > 0; off >>= 1) part += __shfl_xor_sync(0xffffffffu, part, off);
    if (t == 0) { g_rmax[b] = M; g_rsum[b] = part; }
}

/* K8: write soft_full. grid 2048, 256 thr, float4 */
__global__ void __launch_bounds__(256) k_smax_write(float* __restrict__ out) {
    int b = blockIdx.x >> 5, c = blockIdx.x & 31, tid = threadIdx.x;
    const float4* row = (const float4*)(g_sif + (size_t)b * NKEYS + c * 4096);
    float4* orow = (float4*)(out + 2 * BB * K_MAX + (size_t)b * NKEYS + c * 4096);
    float M = g_rmax[b], inv = 1.f / g_rsum[b];
#pragma unroll
    for (int i = 0; i < 4; i++) {
        float4 v = row[tid + 256 * i];
        orow[tid + 256 * i] = make_float4(__expf(v.x - M) * inv, __expf(v.y - M) * inv,
                                          __expf(v.z - M) * inv, __expf(v.w - M) * inv);
    }
}

/* K9: refine + top-64 + alphas. grid 64, 256 thr. Cached local max per thread. */
__global__ void __launch_bounds__(256) k_refine(const float* __restrict__ taup,
                                                const float* __restrict__ lamp,
                                                const int* __restrict__ warmp,
                                                float* __restrict__ out) {
    int b = blockIdx.x, tid = threadIdx.x;
    int wid = tid >> 5, lane = tid & 31;
    __shared__ float raw[M_CAND];
    __shared__ float bvw[256];
    __shared__ float wv[8]; __shared__ int wi[8];
    __shared__ float win_v; __shared__ int win_i;
    __shared__ float vals[K_MAX];
    __shared__ int   gids[K_MAX];
    __shared__ float sD;
    float tau = taup[0], lam = lamp[0];
    int warm = warmp[0];

    float lsum = 0.f;
    for (int r = 0; r < 16; r++) {
        int i = tid + 256 * r;
        int cl = g_topc[b * M_TOP + (i >> 7)];
        float si = g_sif[(size_t)b * NKEYS + cl * NPC + (i & 127)];
        float v;
        if (warm) v = si;
        else {
            float g = 1.f / (1.f + expf(-lam * (si - tau)));
            v = g * expf(si);
        }
        raw[i] = v;
        lsum += v;
    }
    bvw[tid] = lsum; __syncthreads();
    for (int off = 128; off > 0; off >>= 1) {
        if (tid < off) bvw[tid] += bvw[tid + off];
        __syncthreads();
    }
    if (tid == 0) sD = bvw[0] + EPSF;
    __syncthreads();
    if (!warm) {
        float invD = 1.f / sD;
        for (int r = 0; r < 16; r++) raw[tid + 256 * r] *= invD;
    }
    __syncthreads();

    float lv = -FLT_MAX; int li = tid;
    for (int r = 0; r < 16; r++) {
        int i = tid + 256 * r;
        float v = raw[i];
        if (v > lv) { lv = v; li = i; }
    }
    for (int rr = 0; rr < K_MAX; rr++) {
        float bv = lv; int bidx = li;
#pragma unroll
        for (int off = 16; off > 0; off >>= 1) {
            float ov = __shfl_xor_sync(0xffffffffu, bv, off);
            int   oi = __shfl_xor_sync(0xffffffffu, bidx, off);
            if (ov > bv || (ov == bv && oi < bidx)) { bv = ov; bidx = oi; }
        }
        if (lane == 0) { wv[wid] = bv; wi[wid] = bidx; }
        __syncthreads();
        if (tid == 0) {
            float gbv = wv[0]; int gbi = wi[0];
            for (int w = 1; w < 8; w++) {
                if (wv[w] > gbv || (wv[w] == gbv && wi[w] < gbi)) { gbv = wv[w]; gbi = wi[w]; }
            }
            win_v = gbv; win_i = gbi;
            vals[rr] = gbv;
            gids[rr] = g_topc[b * M_TOP + (gbi >> 7)] * NPC + (gbi & 127);
        }
        __syncthreads();
        if ((win_i & 255) == tid) {
            raw[win_i] = -FLT_MAX;
            lv = -FLT_MAX; li = tid;
            for (int r = 0; r < 16; r++) {
                int i = tid + 256 * r;
                float v = raw[i];
                if (v > lv) { lv = v; li = i; }
            }
        }
        __syncthreads();
    }

    if (tid == 0) {
        float alphas[K_MAX];
        if (warm) {
            float m = -FLT_MAX;
            for (int r = 0; r < K_MAX; r++) m = fmaxf(m, vals[r]);
            float ssum = 0.f;
            for (int r = 0; r < K_MAX; r++) { alphas[r] = expf(vals[r] - m); ssum += alphas[r]; }
            float inv = 1.f / ssum;
            for (int r = 0; r < K_MAX; r++) alphas[r] *= inv;
        } else {
            float ssum = 0.f;
            for (int r = 0; r < K_MAX; r++) ssum += vals[r];
            float inv = 1.f / (ssum + EPSF);
            for (int r = 0; r < K_MAX; r++) alphas[r] = vals[r] * inv;
        }
        for (int r = 0; r < K_MAX; r++) {
            out[b * K_MAX + r] = alphas[r];
            out[BB * K_MAX + b * K_MAX + r] = (float)gids[r];
        }
    }
}

extern "C" void kernel_launch(void* const* d_in, const int* in_sizes, int n_in,
                              void* d_out, int out_size) {
    const float* z    = (const float*)d_in[0];
    const float* keys = (const float*)d_in[1];
    const float* WQ   = (const float*)d_in[2];
    const float* aw   = (const float*)d_in[3];
    const float* tau  = (const float*)d_in[4];
    const float* cent = (const float*)d_in[5];
    const float* lam  = (const float*)d_in[6];
    const int*   warm = (const int*)d_in[7];
    float* out = (float*)d_out;

    static const size_t dense_smem = (size_t)(DK * BB + DK * DN) * sizeof(float); /* 96KB */
    cudaFuncSetAttribute(k_dense, cudaFuncAttributeMaxDynamicSharedMemorySize, (int)dense_smem);

    k_qpart<<<256, 128>>>(WQ, z);
    k_qcombine<<<256, 128>>>(aw);
    k_centroid<<<256, 256>>>(cent);
    k_topc<<<64, 512>>>();
    k_dense<<<NKEYS / DN, 128, dense_smem>>>(keys);
    k_smax_part<<<2048, 256>>>();
    k_smax_comb<<<64, 32>>>();
    k_smax_write<<<2048, 256>>>(out);
    k_refine<<<64, 256>>>(tau, lam, warm, out);
}

// round 6
// speedup vs baseline: 1.5401x; 1.1094x over previous
#include <cuda_runtime.h>
#include <math.h>
#include <float.h>

#define S_ASP 4
#define C_CL  1024
#define NKEYS 131072
#define DK    128
#define DA    2048
#define M_TOP 32
#define K_MAX 64
#define BB    64
#define NPC   128
#define M_CAND 4096
#define EPSF  1e-8f
#define DN    128            /* keys per dense block */

__device__ float g_part[32 * S_ASP * DK * BB];
__device__ float g_qwT [S_ASP * DK * BB];       /* w_s * l2norm(q): [s][k][b] */
__device__ float g_cscore[BB * C_CL];
__device__ int   g_topc [BB * M_TOP];
__device__ float g_sif  [(size_t)BB * NKEYS];   /* 32 MB */
__device__ float g_cmax [BB * 32];
__device__ float g_csum [BB * 32];
__device__ float g_rmax [BB];
__device__ float g_rsum [BB];

/* ---- f32x2 / cp.async helpers ---- */
__device__ __forceinline__ unsigned long long pk2(float a, float b) {
    unsigned long long r;
    asm("mov.b64 %0, {%1, %2};" : "=l"(r) : "r"(__float_as_uint(a)), "r"(__float_as_uint(b)));
    return r;
}
__device__ __forceinline__ void fma2(unsigned long long& d, unsigned long long a,
                                     unsigned long long b) {
    asm("fma.rn.f32x2 %0, %1, %2, %3;" : "=l"(d) : "l"(a), "l"(b), "l"(d));
}
__device__ __forceinline__ void upk2(unsigned long long v, float& lo, float& hi) {
    unsigned int l, h;
    asm("mov.b64 {%0, %1}, %2;" : "=r"(l), "=r"(h) : "l"(v));
    lo = __uint_as_float(l); hi = __uint_as_float(h);
}
__device__ __forceinline__ unsigned smem_u32(const void* p) {
    return (unsigned)__cvta_generic_to_shared(p);
}
__device__ __forceinline__ void cpa4(unsigned d, const void* s) {
    asm volatile("cp.async.ca.shared.global [%0], [%1], 4;" :: "r"(d), "l"(s));
}
__device__ __forceinline__ void cpa16(unsigned d, const void* s) {
    asm volatile("cp.async.ca.shared.global [%0], [%1], 16;" :: "r"(d), "l"(s));
}
__device__ __forceinline__ void cpa_commit() {
    asm volatile("cp.async.commit_group;");
}
__device__ __forceinline__ void cpa_wait0() {
    asm volatile("cp.async.wait_group 0;");
}

/* K1: query GEMM partials. grid 256 = s(4) x ac(32) x kh(2), 128 thr */
__global__ void __launch_bounds__(128) k_qpart(const float* __restrict__ WQ,
                                               const float* __restrict__ z) {
    int bx = blockIdx.x, s = bx >> 6, ac = (bx >> 1) & 31, kh = bx & 1;
    int a0 = ac * 64;
    __shared__ float sW[64 * 65], sZ[64 * 65];
    int tid = threadIdx.x;
    for (int idx = tid; idx < 64 * 64; idx += 128) {
        int kl = idx >> 6, aa = idx & 63;
        sW[kl * 65 + aa] = WQ[(size_t)s * DK * DA + (kh * 64 + kl) * DA + a0 + aa];
    }
    for (int idx = tid; idx < 64 * 64; idx += 128) {
        int b = idx >> 6, aa = idx & 63;
        sZ[b * 65 + aa] = z[b * DA + a0 + aa];
    }
    __syncthreads();
    int krow = tid >> 3, bcol = tid & 7;
    float acc[4][8];
#pragma unroll
    for (int i = 0; i < 4; i++)
#pragma unroll
        for (int j = 0; j < 8; j++) acc[i][j] = 0.f;
    for (int aa = 0; aa < 64; aa++) {
        float qk[4], zb[8];
#pragma unroll
        for (int i = 0; i < 4; i++) qk[i] = sW[(krow * 4 + i) * 65 + aa];
#pragma unroll
        for (int j = 0; j < 8; j++) zb[j] = sZ[(bcol * 8 + j) * 65 + aa];
#pragma unroll
        for (int i = 0; i < 4; i++)
#pragma unroll
            for (int j = 0; j < 8; j++) acc[i][j] = fmaf(qk[i], zb[j], acc[i][j]);
    }
#pragma unroll
    for (int i = 0; i < 4; i++)
#pragma unroll
        for (int j = 0; j < 8; j++)
            g_part[((ac * S_ASP + s) * DK + kh * 64 + krow * 4 + i) * BB + bcol * 8 + j] = acc[i][j];
}

/* K2: combine, l2norm, fold softmax(aspect_weights). grid 256 = s*64+b, 128 thr */
__global__ void __launch_bounds__(128) k_qcombine(const float* __restrict__ aw) {
    int s = blockIdx.x >> 6, b = blockIdx.x & 63, k = threadIdx.x;
    float q = 0.f;
    for (int ac = 0; ac < 32; ac++) q += g_part[((ac * S_ASP + s) * DK + k) * BB + b];
    __shared__ float red[DK];
    red[k] = q * q; __syncthreads();
    for (int off = 64; off > 0; off >>= 1) {
        if (k < off) red[k] += red[k + off];
        __syncthreads();
    }
    float rinv = 1.f / (sqrtf(red[0]) + EPSF);
    float a0 = aw[0], a1 = aw[1], a2 = aw[2], a3 = aw[3];
    float mx = fmaxf(fmaxf(a0, a1), fmaxf(a2, a3));
    float e0 = expf(a0 - mx), e1 = expf(a1 - mx), e2 = expf(a2 - mx), e3 = expf(a3 - mx);
    float ws = (s == 0 ? e0 : s == 1 ? e1 : s == 2 ? e2 : e3) / (e0 + e1 + e2 + e3);
    g_qwT[(s * DK + k) * BB + b] = ws * q * rinv;
}

/* K3: centroid scores. grid 256 (4 centroids each), 256 thr */
__global__ void __launch_bounds__(256) k_centroid(const float* __restrict__ cent) {
    int c0 = blockIdx.x * 4, tid = threadIdx.x;
    __shared__ float sc[4][S_ASP][DK];
    __shared__ float srn[4][S_ASP];
    for (int idx = tid; idx < 4 * S_ASP * DK; idx += 256) {
        int r = idx >> 7, k = idx & 127, c = r >> 2, s = r & 3;
        sc[c][s][k] = cent[((size_t)s * C_CL + c0 + c) * DK + k];
    }
    __syncthreads();
    if (tid < 16) {
        int c = tid >> 2, s = tid & 3;
        float ss = 0.f;
        for (int k = 0; k < DK; k++) { float v = sc[c][s][k]; ss += v * v; }
        srn[c][s] = 1.f / (sqrtf(ss) + EPSF);
    }
    __syncthreads();
    int c = tid >> 6, b = tid & 63;
    float acc = 0.f;
    for (int s = 0; s < S_ASP; s++) {
        float p = 0.f;
#pragma unroll 4
        for (int k = 0; k < DK; k++) p = fmaf(g_qwT[(s * DK + k) * BB + b], sc[c][s][k], p);
        acc = fmaf(p, srn[c][s], acc);
    }
    g_cscore[b * C_CL + c0 + c] = acc;
}

/* K4: top-32 of 1024 via full bitonic sort of packed (score,idx) keys. */
__global__ void __launch_bounds__(512) k_topc() {
    int b = blockIdx.x, tid = threadIdx.x;
    __shared__ unsigned long long key[C_CL];
#pragma unroll
    for (int r = 0; r < 2; r++) {
        int i = tid + 512 * r;
        float v = g_cscore[b * C_CL + i];
        unsigned int u = __float_as_uint(v);
        u ^= (u & 0x80000000u) ? 0xFFFFFFFFu : 0x80000000u;
        unsigned int su = ~u;
        key[i] = ((unsigned long long)su << 32) | (unsigned int)i;
    }
    __syncthreads();
    for (int size = 2; size <= C_CL; size <<= 1) {
        for (int stride = size >> 1; stride > 0; stride >>= 1) {
            int i = ((tid & ~(stride - 1)) << 1) | (tid & (stride - 1));
            int j = i + stride;
            bool up = ((i & size) == 0);
            unsigned long long a = key[i], c = key[j];
            bool sw = up ? (a > c) : (a < c);
            if (sw) { key[i] = c; key[j] = a; }
            __syncthreads();
        }
    }
    if (tid < M_TOP) g_topc[b * M_TOP + tid] = (int)(key[tid] & 0xFFFFFFFFu);
}

/* K5: dense pass. grid 1024 (128 keys/block), 256 thr, thread tile 8b x 4n.
   cp.async double-buffered tiles; key smem layout: (n,k) at word k*DN + (n^(k&31)).
   smem: 2 x (q 32KB) + 2 x (keys 64KB) + srn 512B = 192.5KB -> 1 block/SM. */
__global__ void __launch_bounds__(256) k_dense(const float* __restrict__ keys) {
    extern __shared__ float sm[];
    float* sq0 = sm;
    float* sq1 = sm + DK * BB;
    float* sk0 = sm + 2 * DK * BB;
    float* sk1 = sm + 2 * DK * BB + DK * DN;
    float* srn = sm + 2 * DK * BB + 2 * DK * DN;

    int tid = threadIdx.x;
    int brow = tid >> 5;           /* 0..7 : b = 8*brow + 2i + p */
    int ncol = tid & 31;           /* n_j = ncol + 32*j */
    int n0 = blockIdx.x * DN;
    int kk = tid & 127, hh = tid >> 7;   /* loader roles */

    unsigned long long facc[4][4];
#pragma unroll
    for (int j = 0; j < 4; j++)
#pragma unroll
        for (int i = 0; i < 4; i++) facc[j][i] = 0ull;

    /* prologue: load s=0 into buffer 0 */
    {
        const char* qsrc = (const char*)(g_qwT);
        unsigned qd = smem_u32(sq0);
#pragma unroll
        for (int i = 0; i < 8; i++) {
            int c = tid + 256 * i;
            cpa16(qd + c * 16, qsrc + c * 16);
        }
        const float* kb = keys + (size_t)n0 * DK;
        unsigned kd = smem_u32(sk0);
#pragma unroll 8
        for (int r0 = 0; r0 < 64; r0++) {
            int r = hh * 64 + r0;
            cpa4(kd + (kk * DN + (r ^ (kk & 31))) * 4, kb + (size_t)r * DK + kk);
        }
        cpa_commit();
        cpa_wait0();
    }
    __syncthreads();

    int cur = 0;
    for (int s = 0; s < S_ASP; s++) {
        float* sq_c = cur ? sq1 : sq0;
        float* sk_c = cur ? sk1 : sk0;
        /* prefetch next s into other buffer */
        if (s < S_ASP - 1) {
            float* sq_n = cur ? sq0 : sq1;
            float* sk_n = cur ? sk0 : sk1;
            const char* qsrc = (const char*)(g_qwT + (s + 1) * DK * BB);
            unsigned qd = smem_u32(sq_n);
#pragma unroll
            for (int i = 0; i < 8; i++) {
                int c = tid + 256 * i;
                cpa16(qd + c * 16, qsrc + c * 16);
            }
            const float* kb = keys + ((size_t)(s + 1) * NKEYS + n0) * DK;
            unsigned kd = smem_u32(sk_n);
#pragma unroll 8
            for (int r0 = 0; r0 < 64; r0++) {
                int r = hh * 64 + r0;
                cpa4(kd + (kk * DN + (r ^ (kk & 31))) * 4, kb + (size_t)r * DK + kk);
            }
            cpa_commit();
        }
        /* per-key inverse norms (threads 0..127, one key each) */
        if (tid < DN) {
            float ss = 0.f;
#pragma unroll 8
            for (int k = 0; k < DK; k++) {
                float v = sk_c[k * DN + (tid ^ (k & 31))];
                ss = fmaf(v, v, ss);
            }
            srn[tid] = 1.f / (sqrtf(ss) + EPSF);
        }
        __syncthreads();

        unsigned long long accp[4][4];
#pragma unroll
        for (int j = 0; j < 4; j++)
#pragma unroll
            for (int i = 0; i < 4; i++) accp[j][i] = 0ull;

#pragma unroll 4
        for (int k = 0; k < DK; k++) {
            const float* qrow = sq_c + k * BB + (brow << 3);
            ulonglong2 qA = *(const ulonglong2*)(qrow);       /* (b0,b1),(b2,b3) */
            ulonglong2 qB = *(const ulonglong2*)(qrow + 4);   /* (b4,b5),(b6,b7) */
            int kx = k & 31;
            const float* krow = sk_c + k * DN;
            float k0 = krow[(ncol)       ^ kx];
            float k1 = krow[(ncol + 32)  ^ kx];
            float k2 = krow[(ncol + 64)  ^ kx];
            float k3 = krow[(ncol + 96)  ^ kx];
            unsigned long long kd0 = pk2(k0, k0);
            unsigned long long kd1 = pk2(k1, k1);
            unsigned long long kd2 = pk2(k2, k2);
            unsigned long long kd3 = pk2(k3, k3);
            fma2(accp[0][0], qA.x, kd0); fma2(accp[0][1], qA.y, kd0);
            fma2(accp[0][2], qB.x, kd0); fma2(accp[0][3], qB.y, kd0);
            fma2(accp[1][0], qA.x, kd1); fma2(accp[1][1], qA.y, kd1);
            fma2(accp[1][2], qB.x, kd1); fma2(accp[1][3], qB.y, kd1);
            fma2(accp[2][0], qA.x, kd2); fma2(accp[2][1], qA.y, kd2);
            fma2(accp[2][2], qB.x, kd2); fma2(accp[2][3], qB.y, kd2);
            fma2(accp[3][0], qA.x, kd3); fma2(accp[3][1], qA.y, kd3);
            fma2(accp[3][2], qB.x, kd3); fma2(accp[3][3], qB.y, kd3);
        }
        /* fold per-key norm into running total */
#pragma unroll
        for (int j = 0; j < 4; j++) {
            float rnj = srn[ncol + 32 * j];
            unsigned long long rd = pk2(rnj, rnj);
#pragma unroll
            for (int i = 0; i < 4; i++) fma2(facc[j][i], accp[j][i], rd);
        }
        cpa_wait0();
        __syncthreads();
        cur ^= 1;
    }

#pragma unroll
    for (int j = 0; j < 4; j++)
#pragma unroll
        for (int i = 0; i < 4; i++) {
            float v0, v1;
            upk2(facc[j][i], v0, v1);
            size_t base = (size_t)(brow * 8 + 2 * i) * NKEYS + n0 + ncol + 32 * j;
            g_sif[base] = v0;
            g_sif[base + NKEYS] = v1;
        }
}

/* K6: per-chunk softmax stats. grid 2048 = b*32+c, 256 thr, float4 */
__global__ void __launch_bounds__(256) k_smax_part() {
    int b = blockIdx.x >> 5, c = blockIdx.x & 31, tid = threadIdx.x;
    const float4* row = (const float4*)(g_sif + (size_t)b * NKEYS + c * 4096);
    float4 v[4];
    float m = -FLT_MAX;
#pragma unroll
    for (int i = 0; i < 4; i++) {
        v[i] = row[tid + 256 * i];
        m = fmaxf(m, fmaxf(fmaxf(v[i].x, v[i].y), fmaxf(v[i].z, v[i].w)));
    }
    __shared__ float smem[256];
    smem[tid] = m; __syncthreads();
    for (int off = 128; off > 0; off >>= 1) {
        if (tid < off) smem[tid] = fmaxf(smem[tid], smem[tid + off]);
        __syncthreads();
    }
    float bm = smem[0]; __syncthreads();
    float sum = 0.f;
#pragma unroll
    for (int i = 0; i < 4; i++)
        sum += __expf(v[i].x - bm) + __expf(v[i].y - bm) + __expf(v[i].z - bm) + __expf(v[i].w - bm);
    smem[tid] = sum; __syncthreads();
    for (int off = 128; off > 0; off >>= 1) {
        if (tid < off) smem[tid] += smem[tid + off];
        __syncthreads();
    }
    if (tid == 0) { g_cmax[b * 32 + c] = bm; g_csum[b * 32 + c] = smem[0]; }
}

/* K7: combine chunk stats. grid 64, 32 thr */
__global__ void __launch_bounds__(32) k_smax_comb() {
    int b = blockIdx.x, t = threadIdx.x;
    float m = g_cmax[b * 32 + t], s = g_csum[b * 32 + t];
    float M = m;
    for (int off = 16; off > 0; off >>= 1) M = fmaxf(M, __shfl_xor_sync(0xffffffffu, M, off));
    float part = s * __expf(m - M);
    for (int off = 16; off > 0; off >>= 1) part += __shfl_xor_sync(0xffffffffu, part, off);
    if (t == 0) { g_rmax[b] = M; g_rsum[b] = part; }
}

/* K8: write soft_full. grid 2048, 256 thr, float4 */
__global__ void __launch_bounds__(256) k_smax_write(float* __restrict__ out) {
    int b = blockIdx.x >> 5, c = blockIdx.x & 31, tid = threadIdx.x;
    const float4* row = (const float4*)(g_sif + (size_t)b * NKEYS + c * 4096);
    float4* orow = (float4*)(out + 2 * BB * K_MAX + (size_t)b * NKEYS + c * 4096);
    float M = g_rmax[b], inv = 1.f / g_rsum[b];
#pragma unroll
    for (int i = 0; i < 4; i++) {
        float4 v = row[tid + 256 * i];
        orow[tid + 256 * i] = make_float4(__expf(v.x - M) * inv, __expf(v.y - M) * inv,
                                          __expf(v.z - M) * inv, __expf(v.w - M) * inv);
    }
}

/* K9: refine + top-64 + alphas. grid 64, 256 thr. Cached local max per thread. */
__global__ void __launch_bounds__(256) k_refine(const float* __restrict__ taup,
                                                const float* __restrict__ lamp,
                                                const int* __restrict__ warmp,
                                                float* __restrict__ out) {
    int b = blockIdx.x, tid = threadIdx.x;
    int wid = tid >> 5, lane = tid & 31;
    __shared__ float raw[M_CAND];
    __shared__ float bvw[256];
    __shared__ float wv[8]; __shared__ int wi[8];
    __shared__ float win_v; __shared__ int win_i;
    __shared__ float vals[K_MAX];
    __shared__ int   gids[K_MAX];
    __shared__ float sD;
    float tau = taup[0], lam = lamp[0];
    int warm = warmp[0];

    float lsum = 0.f;
    for (int r = 0; r < 16; r++) {
        int i = tid + 256 * r;
        int cl = g_topc[b * M_TOP + (i >> 7)];
        float si = g_sif[(size_t)b * NKEYS + cl * NPC + (i & 127)];
        float v;
        if (warm) v = si;
        else {
            float g = 1.f / (1.f + expf(-lam * (si - tau)));
            v = g * expf(si);
        }
        raw[i] = v;
        lsum += v;
    }
    bvw[tid] = lsum; __syncthreads();
    for (int off = 128; off > 0; off >>= 1) {
        if (tid < off) bvw[tid] += bvw[tid + off];
        __syncthreads();
    }
    if (tid == 0) sD = bvw[0] + EPSF;
    __syncthreads();
    if (!warm) {
        float invD = 1.f / sD;
        for (int r = 0; r < 16; r++) raw[tid + 256 * r] *= invD;
    }
    __syncthreads();

    float lv = -FLT_MAX; int li = tid;
    for (int r = 0; r < 16; r++) {
        int i = tid + 256 * r;
        float v = raw[i];
        if (v > lv) { lv = v; li = i; }
    }
    for (int rr = 0; rr < K_MAX; rr++) {
        float bv = lv; int bidx = li;
#pragma unroll
        for (int off = 16; off > 0; off >>= 1) {
            float ov = __shfl_xor_sync(0xffffffffu, bv, off);
            int   oi = __shfl_xor_sync(0xffffffffu, bidx, off);
            if (ov > bv || (ov == bv && oi < bidx)) { bv = ov; bidx = oi; }
        }
        if (lane == 0) { wv[wid] = bv; wi[wid] = bidx; }
        __syncthreads();
        if (tid == 0) {
            float gbv = wv[0]; int gbi = wi[0];
            for (int w = 1; w < 8; w++) {
                if (wv[w] > gbv || (wv[w] == gbv && wi[w] < gbi)) { gbv = wv[w]; gbi = wi[w]; }
            }
            win_v = gbv; win_i = gbi;
            vals[rr] = gbv;
            gids[rr] = g_topc[b * M_TOP + (gbi >> 7)] * NPC + (gbi & 127);
        }
        __syncthreads();
        if ((win_i & 255) == tid) {
            raw[win_i] = -FLT_MAX;
            lv = -FLT_MAX; li = tid;
            for (int r = 0; r < 16; r++) {
                int i = tid + 256 * r;
                float v = raw[i];
                if (v > lv) { lv = v; li = i; }
            }
        }
        __syncthreads();
    }

    if (tid == 0) {
        float alphas[K_MAX];
        if (warm) {
            float m = -FLT_MAX;
            for (int r = 0; r < K_MAX; r++) m = fmaxf(m, vals[r]);
            float ssum = 0.f;
            for (int r = 0; r < K_MAX; r++) { alphas[r] = expf(vals[r] - m); ssum += alphas[r]; }
            float inv = 1.f / ssum;
            for (int r = 0; r < K_MAX; r++) alphas[r] *= inv;
        } else {
            float ssum = 0.f;
            for (int r = 0; r < K_MAX; r++) ssum += vals[r];
            float inv = 1.f / (ssum + EPSF);
            for (int r = 0; r < K_MAX; r++) alphas[r] = vals[r] * inv;
        }
        for (int r = 0; r < K_MAX; r++) {
            out[b * K_MAX + r] = alphas[r];
            out[BB * K_MAX + b * K_MAX + r] = (float)gids[r];
        }
    }
}

extern "C" void kernel_launch(void* const* d_in, const int* in_sizes, int n_in,
                              void* d_out, int out_size) {
    const float* z    = (const float*)d_in[0];
    const float* keys = (const float*)d_in[1];
    const float* WQ   = (const float*)d_in[2];
    const float* aw   = (const float*)d_in[3];
    const float* tau  = (const float*)d_in[4];
    const float* cent = (const float*)d_in[5];
    const float* lam  = (const float*)d_in[6];
    const int*   warm = (const int*)d_in[7];
    float* out = (float*)d_out;

    static const size_t dense_smem =
        (size_t)(2 * DK * BB + 2 * DK * DN + DN) * sizeof(float);  /* 192.5 KB */
    cudaFuncSetAttribute(k_dense, cudaFuncAttributeMaxDynamicSharedMemorySize, (int)dense_smem);

    k_qpart<<<256, 128>>>(WQ, z);
    k_qcombine<<<256, 128>>>(aw);
    k_centroid<<<256, 256>>>(cent);
    k_topc<<<64, 512>>>();
    k_dense<<<NKEYS / DN, 256, dense_smem>>>(keys);
    k_smax_part<<<2048, 256>>>();
    k_smax_comb<<<64, 32>>>();
    k_smax_write<<<2048, 256>>>(out);
    k_refine<<<64, 256>>>(tau, lam, warm, out);
}

// round 9
// speedup vs baseline: 1.5409x; 1.0005x over previous
#include <cuda_runtime.h>
#include <math.h>
#include <float.h>
#include <stdint.h>

#define S_ASP 4
#define C_CL  1024
#define NKEYS 131072
#define DK    128
#define DA    2048
#define M_TOP 32
#define K_MAX 64
#define BB    64
#define NPC   128
#define M_CAND 4096
#define EPSF  1e-8f
#define DN    128            /* keys per MMA block */

__device__ float g_part[32 * S_ASP * DK * BB];
__device__ float g_qwT [S_ASP * DK * BB];       /* [s][k][b] for centroid kernel */
__device__ float g_qbk [S_ASP * BB * DK];       /* [s][b][k] for MMA B + exact */
__device__ float g_cscore[BB * C_CL];
__device__ int   g_topc [BB * M_TOP];
__device__ float g_sif  [(size_t)BB * NKEYS];   /* 32 MB, tf32 accuracy */
__device__ float g_refS [BB * M_CAND];          /* exact fp32 candidate scores */
__device__ unsigned long long g_clmask[C_CL];
__device__ int   g_rank [C_CL * BB];
__device__ float g_cmax [BB * 32];
__device__ float g_csum [BB * 32];
__device__ float g_rmax [BB];
__device__ float g_rsum [BB];

/* ---- warp mma tf32 m16n8k8: D += A(16x8) * B(8x8) ---- */
__device__ __forceinline__ void mma_tf32(float* c, const unsigned* a, const unsigned* b) {
    asm volatile("mma.sync.aligned.m16n8k8.row.col.f32.tf32.tf32.f32 "
                 "{%0,%1,%2,%3}, {%4,%5,%6,%7}, {%8,%9}, {%0,%1,%2,%3};"
                 : "+f"(c[0]), "+f"(c[1]), "+f"(c[2]), "+f"(c[3])
                 : "r"(a[0]), "r"(a[1]), "r"(a[2]), "r"(a[3]), "r"(b[0]), "r"(b[1]));
}

/* K1: query GEMM partials. grid 256 = s(4) x ac(32) x kh(2), 128 thr */
__global__ void __launch_bounds__(128) k_qpart(const float* __restrict__ WQ,
                                               const float* __restrict__ z) {
    int bx = blockIdx.x, s = bx >> 6, ac = (bx >> 1) & 31, kh = bx & 1;
    int a0 = ac * 64;
    __shared__ float sW[64 * 65], sZ[64 * 65];
    int tid = threadIdx.x;
    for (int idx = tid; idx < 64 * 64; idx += 128) {
        int kl = idx >> 6, aa = idx & 63;
        sW[kl * 65 + aa] = WQ[(size_t)s * DK * DA + (kh * 64 + kl) * DA + a0 + aa];
    }
    for (int idx = tid; idx < 64 * 64; idx += 128) {
        int b = idx >> 6, aa = idx & 63;
        sZ[b * 65 + aa] = z[b * DA + a0 + aa];
    }
    __syncthreads();
    int krow = tid >> 3, bcol = tid & 7;
    float acc[4][8];
#pragma unroll
    for (int i = 0; i < 4; i++)
#pragma unroll
        for (int j = 0; j < 8; j++) acc[i][j] = 0.f;
    for (int aa = 0; aa < 64; aa++) {
        float qk[4], zb[8];
#pragma unroll
        for (int i = 0; i < 4; i++) qk[i] = sW[(krow * 4 + i) * 65 + aa];
#pragma unroll
        for (int j = 0; j < 8; j++) zb[j] = sZ[(bcol * 8 + j) * 65 + aa];
#pragma unroll
        for (int i = 0; i < 4; i++)
#pragma unroll
            for (int j = 0; j < 8; j++) acc[i][j] = fmaf(qk[i], zb[j], acc[i][j]);
    }
#pragma unroll
    for (int i = 0; i < 4; i++)
#pragma unroll
        for (int j = 0; j < 8; j++)
            g_part[((ac * S_ASP + s) * DK + kh * 64 + krow * 4 + i) * BB + bcol * 8 + j] = acc[i][j];
}

/* K2: combine + l2norm + aspect softmax weight */
__global__ void __launch_bounds__(128) k_qcombine(const float* __restrict__ aw) {
    int s = blockIdx.x >> 6, b = blockIdx.x & 63, k = threadIdx.x;
    float q = 0.f;
    for (int ac = 0; ac < 32; ac++) q += g_part[((ac * S_ASP + s) * DK + k) * BB + b];
    __shared__ float red[DK];
    red[k] = q * q; __syncthreads();
    for (int off = 64; off > 0; off >>= 1) {
        if (k < off) red[k] += red[k + off];
        __syncthreads();
    }
    float rinv = 1.f / (sqrtf(red[0]) + EPSF);
    float a0 = aw[0], a1 = aw[1], a2 = aw[2], a3 = aw[3];
    float mx = fmaxf(fmaxf(a0, a1), fmaxf(a2, a3));
    float e0 = expf(a0 - mx), e1 = expf(a1 - mx), e2 = expf(a2 - mx), e3 = expf(a3 - mx);
    float ws = (s == 0 ? e0 : s == 1 ? e1 : s == 2 ? e2 : e3) / (e0 + e1 + e2 + e3);
    float v = ws * q * rinv;
    g_qwT[(s * DK + k) * BB + b] = v;
    g_qbk[(s * BB + b) * DK + k] = v;
}

/* K3: centroid scores. grid 256 (4 centroids each), 256 thr */
__global__ void __launch_bounds__(256) k_centroid(const float* __restrict__ cent) {
    int c0 = blockIdx.x * 4, tid = threadIdx.x;
    __shared__ float sc[4][S_ASP][DK];
    __shared__ float srn[4][S_ASP];
    for (int idx = tid; idx < 4 * S_ASP * DK; idx += 256) {
        int r = idx >> 7, k = idx & 127, c = r >> 2, s = r & 3;
        sc[c][s][k] = cent[((size_t)s * C_CL + c0 + c) * DK + k];
    }
    __syncthreads();
    if (tid < 16) {
        int c = tid >> 2, s = tid & 3;
        float ss = 0.f;
        for (int k = 0; k < DK; k++) { float v = sc[c][s][k]; ss += v * v; }
        srn[c][s] = 1.f / (sqrtf(ss) + EPSF);
    }
    __syncthreads();
    int c = tid >> 6, b = tid & 63;
    float acc = 0.f;
    for (int s = 0; s < S_ASP; s++) {
        float p = 0.f;
#pragma unroll 4
        for (int k = 0; k < DK; k++) p = fmaf(g_qwT[(s * DK + k) * BB + b], sc[c][s][k], p);
        acc = fmaf(p, srn[c][s], acc);
    }
    g_cscore[b * C_CL + c0 + c] = acc;
}

/* K4: top-32 of 1024 via bitonic sort of packed (score,idx). grid 64, 512 thr */
__global__ void __launch_bounds__(512) k_topc() {
    int b = blockIdx.x, tid = threadIdx.x;
    __shared__ unsigned long long key[C_CL];
#pragma unroll
    for (int r = 0; r < 2; r++) {
        int i = tid + 512 * r;
        float v = g_cscore[b * C_CL + i];
        unsigned int u = __float_as_uint(v);
        u ^= (u & 0x80000000u) ? 0xFFFFFFFFu : 0x80000000u;
        unsigned int su = ~u;
        key[i] = ((unsigned long long)su << 32) | (unsigned int)i;
    }
    __syncthreads();
    for (int size = 2; size <= C_CL; size <<= 1) {
        for (int stride = size >> 1; stride > 0; stride >>= 1) {
            int i = ((tid & ~(stride - 1)) << 1) | (tid & (stride - 1));
            int j = i + stride;
            bool up = ((i & size) == 0);
            unsigned long long a = key[i], c = key[j];
            bool sw = up ? (a > c) : (a < c);
            if (sw) { key[i] = c; key[j] = a; }
            __syncthreads();
        }
    }
    if (tid < M_TOP) g_topc[b * M_TOP + tid] = (int)(key[tid] & 0xFFFFFFFFu);
}

__global__ void __launch_bounds__(256) k_clzero() {
    int i = blockIdx.x * 256 + threadIdx.x;
    if (i < C_CL) g_clmask[i] = 0ull;
}
__global__ void __launch_bounds__(32) k_clmask() {
    int b = blockIdx.x, r = threadIdx.x;
    int c = g_topc[b * M_TOP + r];
    atomicOr(&g_clmask[c], 1ull << b);
    g_rank[c * BB + b] = r;
}

/* K5: tf32 warp-mma dense pass. grid 1024 (128 keys), 256 thr.
   smem floats: sk0 16384, sk1 16384, sq0 8192, sq1 8192, srn 128 = 197 KB.
   key tile layout: sk[row*128 + (k ^ (4*(row&7)))]; q tile sq[n*128 + (k ^ 4*(n&7))].
   warp w: wm = w&3 (32 key rows), wn = w>>2 (32 b cols); 2 M-tiles x 4 N-tiles. */
__global__ void __launch_bounds__(256, 1) k_mma(const float* __restrict__ keys) {
    extern __shared__ float sm[];
    float* sk0 = sm;
    float* sk1 = sm + 16384;
    float* sq0 = sm + 32768;
    float* sq1 = sm + 40960;
    float* srn = sm + 49152;

    int tid = threadIdx.x, wid = tid >> 5, lane = tid & 31;
    int wm = wid & 3, wn = wid >> 2;
    int g = lane >> 2, j = lane & 3;
    int n0 = blockIdx.x * DN;

    float acc[2][4][4];
#pragma unroll
    for (int mt = 0; mt < 2; mt++)
#pragma unroll
        for (int nt = 0; nt < 4; nt++)
#pragma unroll
            for (int c = 0; c < 4; c++) acc[mt][nt][c] = 0.f;

    /* fill indices (fixed per thread) */
    int krow[16], kcol[16], qn[8], qk[8];
#pragma unroll
    for (int i = 0; i < 16; i++) {
        int idx = tid + 256 * i;
        krow[i] = idx >> 5; kcol[i] = (idx & 31) << 2;
    }
#pragma unroll
    for (int i = 0; i < 8; i++) {
        int idx = tid + 256 * i;
        qn[i] = idx >> 5; qk[i] = (idx & 31) << 2;
    }

    /* load s=0 */
    {
        const float* kb = keys + (size_t)n0 * DK;
#pragma unroll
        for (int i = 0; i < 16; i++) {
            float4 v = *(const float4*)(kb + (size_t)krow[i] * DK + kcol[i]);
            *(float4*)(sk0 + krow[i] * DK + (kcol[i] ^ (4 * (krow[i] & 7)))) = v;
        }
#pragma unroll
        for (int i = 0; i < 8; i++) {
            float4 v = *(const float4*)(g_qbk + (size_t)qn[i] * DK + qk[i]);
            *(float4*)(sq0 + qn[i] * DK + (qk[i] ^ (4 * (qn[i] & 7)))) = v;
        }
    }
    __syncthreads();

    int cur = 0;
    for (int s = 0; s < S_ASP; s++) {
        float* sk = cur ? sk1 : sk0;
        float* sq = cur ? sq1 : sq0;
        float4 stgK[16]; float4 stgQ[8];
        if (s < S_ASP - 1) {
            const float* kb = keys + ((size_t)(s + 1) * NKEYS + n0) * DK;
#pragma unroll
            for (int i = 0; i < 16; i++)
                stgK[i] = *(const float4*)(kb + (size_t)krow[i] * DK + kcol[i]);
            const float* qb = g_qbk + (size_t)(s + 1) * BB * DK;
#pragma unroll
            for (int i = 0; i < 8; i++)
                stgQ[i] = *(const float4*)(qb + (size_t)qn[i] * DK + qk[i]);
        }
        /* per-key inverse norms: 2 threads per row */
        {
            int row = tid >> 1, half = tid & 1;
            int sw = 4 * (row & 7);
            float ss = 0.f;
#pragma unroll
            for (int i = 0; i < 16; i++) {
                int kf = half * 64 + i * 4;
                float4 v = *(const float4*)(sk + row * DK + (kf ^ sw));
                ss += v.x * v.x + v.y * v.y + v.z * v.z + v.w * v.w;
            }
            ss += __shfl_xor_sync(0xffffffffu, ss, 1);
            if (half == 0) srn[row] = 1.f / (sqrtf(ss) + EPSF);
        }
        /* stage next tiles into alternate buffers */
        if (s < S_ASP - 1) {
            float* skn = cur ? sk0 : sk1;
            float* sqn = cur ? sq0 : sq1;
#pragma unroll
            for (int i = 0; i < 16; i++)
                *(float4*)(skn + krow[i] * DK + (kcol[i] ^ (4 * (krow[i] & 7)))) = stgK[i];
#pragma unroll
            for (int i = 0; i < 8; i++)
                *(float4*)(sqn + qn[i] * DK + (qk[i] ^ (4 * (qn[i] & 7)))) = stgQ[i];
        }
        __syncthreads();   /* srn ready; next tiles staged */

        float rn0[2], rn1[2];
#pragma unroll
        for (int mt = 0; mt < 2; mt++) {
            rn0[mt] = srn[wm * 32 + mt * 16 + g];
            rn1[mt] = srn[wm * 32 + mt * 16 + 8 + g];
        }
#pragma unroll
        for (int kt = 0; kt < 16; kt++) {
            int k0 = kt * 8;
            unsigned bf[4][2];
#pragma unroll
            for (int nt = 0; nt < 4; nt++) {
                int n = wn * 32 + nt * 8 + g;
                int sw = 4 * (n & 7);
                bf[nt][0] = __float_as_uint(sq[n * DK + ((k0 + j) ^ sw)]);
                bf[nt][1] = __float_as_uint(sq[n * DK + ((k0 + 4 + j) ^ sw)]);
            }
            unsigned af[2][4];
#pragma unroll
            for (int mt = 0; mt < 2; mt++) {
                int r = wm * 32 + mt * 16 + g;
                int sw = 4 * (r & 7);
                af[mt][0] = __float_as_uint(sk[r * DK + ((k0 + j) ^ sw)] * rn0[mt]);
                af[mt][1] = __float_as_uint(sk[(r + 8) * DK + ((k0 + j) ^ sw)] * rn1[mt]);
                af[mt][2] = __float_as_uint(sk[r * DK + ((k0 + 4 + j) ^ sw)] * rn0[mt]);
                af[mt][3] = __float_as_uint(sk[(r + 8) * DK + ((k0 + 4 + j) ^ sw)] * rn1[mt]);
            }
#pragma unroll
            for (int mt = 0; mt < 2; mt++)
#pragma unroll
                for (int nt = 0; nt < 4; nt++)
                    mma_tf32(acc[mt][nt], af[mt], bf[nt]);
        }
        __syncthreads();   /* done reading cur before next aspect overwrites it */
        cur ^= 1;
    }

    /* epilogue: c0:(key=base+g, b=bb+2j) c1:(b+1) c2:(key+8) c3:(key+8,b+1) */
#pragma unroll
    for (int mt = 0; mt < 2; mt++) {
        int keyr = n0 + wm * 32 + mt * 16 + g;
#pragma unroll
        for (int nt = 0; nt < 4; nt++) {
            int b = wn * 32 + nt * 8 + 2 * j;
            g_sif[(size_t)b * NKEYS + keyr]           = acc[mt][nt][0];
            g_sif[(size_t)(b + 1) * NKEYS + keyr]     = acc[mt][nt][1];
            g_sif[(size_t)b * NKEYS + keyr + 8]       = acc[mt][nt][2];
            g_sif[(size_t)(b + 1) * NKEYS + keyr + 8] = acc[mt][nt][3];
        }
    }
}

/* K5b: exact fp32 candidate scores, cluster-inverted. grid 1024, 256 thr. */
__global__ void __launch_bounds__(256) k_exact(const float* __restrict__ keys) {
    extern __shared__ float es[];
    float* skey = es;                /* [key][k] at key*128 + (k ^ 4*(key&7)) */
    float* qs   = es + 16384;        /* [slot][k] */
    float* acc  = es + 16384 + 8192; /* [slot][key] */
    float* srn  = es + 16384 + 16384;
    int*   bl   = (int*)(es + 16384 + 16384 + 128);

    int c = blockIdx.x, tid = threadIdx.x;
    unsigned long long mask = g_clmask[c];
    if (mask == 0ull) return;
    int nb = __popcll(mask);
    if (tid == 0) {
        unsigned long long m = mask;
        for (int i = 0; i < nb; i++) {
            int b = __ffsll((long long)m) - 1;
            bl[i] = b;
            m &= m - 1;
        }
    }
    for (int i = tid; i < nb * DN; i += 256) acc[i] = 0.f;
    __syncthreads();

    for (int s = 0; s < S_ASP; s++) {
        const float* kb = keys + ((size_t)s * NKEYS + (size_t)c * DN) * DK;
#pragma unroll
        for (int i = 0; i < 16; i++) {
            int idx = tid + 256 * i;
            int row = idx >> 5, kc = (idx & 31) << 2;
            float4 v = *(const float4*)(kb + (size_t)row * DK + kc);
            *(float4*)(skey + row * DK + (kc ^ (4 * (row & 7)))) = v;
        }
        for (int i = tid; i < nb * DK; i += 256) {
            int slot = i >> 7, k = i & 127;
            qs[i] = g_qbk[((size_t)s * BB + bl[slot]) * DK + k];
        }
        __syncthreads();
        {   /* norms: 2 threads per key */
            int row = tid >> 1, half = tid & 1;
            int sw = 4 * (row & 7);
            float ss = 0.f;
#pragma unroll
            for (int i = 0; i < 16; i++) {
                int kf = half * 64 + i * 4;
                float4 v = *(const float4*)(skey + row * DK + (kf ^ sw));
                ss += v.x * v.x + v.y * v.y + v.z * v.z + v.w * v.w;
            }
            ss += __shfl_xor_sync(0xffffffffu, ss, 1);
            if (half == 0) srn[row] = 1.f / (sqrtf(ss) + EPSF);
        }
        __syncthreads();
        for (int p = tid; p < nb * DN; p += 256) {
            int slot = p >> 7, key = p & 127;
            int sw = 4 * (key & 7);
            float d = 0.f;
            const float* qq = qs + slot * DK;
#pragma unroll 8
            for (int k = 0; k < DK; k++)
                d = fmaf(skey[key * DK + (k ^ sw)], qq[k], d);
            acc[p] = fmaf(d, srn[key], acc[p]);
        }
        __syncthreads();
    }
    for (int p = tid; p < nb * DN; p += 256) {
        int slot = p >> 7, key = p & 127;
        int b = bl[slot];
        int rank = g_rank[c * BB + b];
        g_refS[b * M_CAND + rank * DN + key] = acc[p];
    }
}

/* K6: per-chunk softmax stats. grid 2048 = b*32+c, 256 thr, float4 */
__global__ void __launch_bounds__(256) k_smax_part() {
    int b = blockIdx.x >> 5, c = blockIdx.x & 31, tid = threadIdx.x;
    const float4* row = (const float4*)(g_sif + (size_t)b * NKEYS + c * 4096);
    float4 v[4];
    float m = -FLT_MAX;
#pragma unroll
    for (int i = 0; i < 4; i++) {
        v[i] = row[tid + 256 * i];
        m = fmaxf(m, fmaxf(fmaxf(v[i].x, v[i].y), fmaxf(v[i].z, v[i].w)));
    }
    __shared__ float smem[256];
    smem[tid] = m; __syncthreads();
    for (int off = 128; off > 0; off >>= 1) {
        if (tid < off) smem[tid] = fmaxf(smem[tid], smem[tid + off]);
        __syncthreads();
    }
    float bm = smem[0]; __syncthreads();
    float sum = 0.f;
#pragma unroll
    for (int i = 0; i < 4; i++)
        sum += __expf(v[i].x - bm) + __expf(v[i].y - bm) + __expf(v[i].z - bm) + __expf(v[i].w - bm);
    smem[tid] = sum; __syncthreads();
    for (int off = 128; off > 0; off >>= 1) {
        if (tid < off) smem[tid] += smem[tid + off];
        __syncthreads();
    }
    if (tid == 0) { g_cmax[b * 32 + c] = bm; g_csum[b * 32 + c] = smem[0]; }
}

/* K7: combine chunk stats. grid 64, 32 thr */
__global__ void __launch_bounds__(32) k_smax_comb() {
    int b = blockIdx.x, t = threadIdx.x;
    float m = g_cmax[b * 32 + t], s = g_csum[b * 32 + t];
    float M = m;
    for (int off = 16; off > 0; off >>= 1) M = fmaxf(M, __shfl_xor_sync(0xffffffffu, M, off));
    float part = s * __expf(m - M);
    for (int off = 16; off > 0; off >>= 1) part += __shfl_xor_sync(0xffffffffu, part, off);
    if (t == 0) { g_rmax[b] = M; g_rsum[b] = part; }
}

/* K8: write soft_full. grid 2048, 256 thr, float4 */
__global__ void __launch_bounds__(256) k_smax_write(float* __restrict__ out) {
    int b = blockIdx.x >> 5, c = blockIdx.x & 31, tid = threadIdx.x;
    const float4* row = (const float4*)(g_sif + (size_t)b * NKEYS + c * 4096);
    float4* orow = (float4*)(out + 2 * BB * K_MAX + (size_t)b * NKEYS + c * 4096);
    float M = g_rmax[b], inv = 1.f / g_rsum[b];
#pragma unroll
    for (int i = 0; i < 4; i++) {
        float4 v = row[tid + 256 * i];
        orow[tid + 256 * i] = make_float4(__expf(v.x - M) * inv, __expf(v.y - M) * inv,
                                          __expf(v.z - M) * inv, __expf(v.w - M) * inv);
    }
}

/* K9: refine + top-64 + alphas. grid 64, 256 thr. Reads exact scores. */
__global__ void __launch_bounds__(256) k_refine(const float* __restrict__ taup,
                                                const float* __restrict__ lamp,
                                                const int* __restrict__ warmp,
                                                float* __restrict__ out) {
    int b = blockIdx.x, tid = threadIdx.x;
    int wid = tid >> 5, lane = tid & 31;
    __shared__ float raw[M_CAND];
    __shared__ float bvw[256];
    __shared__ float wv[8]; __shared__ int wi[8];
    __shared__ int win_i;
    __shared__ float vals[K_MAX];
    __shared__ int   gids[K_MAX];
    __shared__ float sD;
    float tau = taup[0], lam = lamp[0];
    int warm = warmp[0];

    float lsum = 0.f;
    for (int r = 0; r < 16; r++) {
        int i = tid + 256 * r;
        float si = g_refS[b * M_CAND + i];
        float v;
        if (warm) v = si;
        else {
            float g = 1.f / (1.f + expf(-lam * (si - tau)));
            v = g * expf(si);
        }
        raw[i] = v;
        lsum += v;
    }
    bvw[tid] = lsum; __syncthreads();
    for (int off = 128; off > 0; off >>= 1) {
        if (tid < off) bvw[tid] += bvw[tid + off];
        __syncthreads();
    }
    if (tid == 0) sD = bvw[0] + EPSF;
    __syncthreads();
    if (!warm) {
        float invD = 1.f / sD;
        for (int r = 0; r < 16; r++) raw[tid + 256 * r] *= invD;
    }
    __syncthreads();

    float lv = -FLT_MAX; int li = tid;
    for (int r = 0; r < 16; r++) {
        int i = tid + 256 * r;
        float v = raw[i];
        if (v > lv) { lv = v; li = i; }
    }
    for (int rr = 0; rr < K_MAX; rr++) {
        float bv = lv; int bidx = li;
#pragma unroll
        for (int off = 16; off > 0; off >>= 1) {
            float ov = __shfl_xor_sync(0xffffffffu, bv, off);
            int   oi = __shfl_xor_sync(0xffffffffu, bidx, off);
            if (ov > bv || (ov == bv && oi < bidx)) { bv = ov; bidx = oi; }
        }
        if (lane == 0) { wv[wid] = bv; wi[wid] = bidx; }
        __syncthreads();
        if (tid == 0) {
            float gbv = wv[0]; int gbi = wi[0];
            for (int w = 1; w < 8; w++) {
                if (wv[w] > gbv || (wv[w] == gbv && wi[w] < gbi)) { gbv = wv[w]; gbi = wi[w]; }
            }
            win_i = gbi;
            vals[rr] = gbv;
            gids[rr] = g_topc[b * M_TOP + (gbi >> 7)] * NPC + (gbi & 127);
        }
        __syncthreads();
        if ((win_i & 255) == tid) {
            raw[win_i] = -FLT_MAX;
            lv = -FLT_MAX; li = tid;
            for (int r = 0; r < 16; r++) {
                int i = tid + 256 * r;
                float v = raw[i];
                if (v > lv) { lv = v; li = i; }
            }
        }
        __syncthreads();
    }

    if (tid == 0) {
        float alphas[K_MAX];
        if (warm) {
            float m = -FLT_MAX;
            for (int r = 0; r < K_MAX; r++) m = fmaxf(m, vals[r]);
            float ssum = 0.f;
            for (int r = 0; r < K_MAX; r++) { alphas[r] = expf(vals[r] - m); ssum += alphas[r]; }
            float inv = 1.f / ssum;
            for (int r = 0; r < K_MAX; r++) alphas[r] *= inv;
        } else {
            float ssum = 0.f;
            for (int r = 0; r < K_MAX; r++) ssum += vals[r];
            float inv = 1.f / (ssum + EPSF);
            for (int r = 0; r < K_MAX; r++) alphas[r] = vals[r] * inv;
        }
        for (int r = 0; r < K_MAX; r++) {
            out[b * K_MAX + r] = alphas[r];
            out[BB * K_MAX + b * K_MAX + r] = (float)gids[r];
        }
    }
}

extern "C" void kernel_launch(void* const* d_in, const int* in_sizes, int n_in,
                              void* d_out, int out_size) {
    const float* z    = (const float*)d_in[0];
    const float* keys = (const float*)d_in[1];
    const float* WQ   = (const float*)d_in[2];
    const float* aw   = (const float*)d_in[3];
    const float* tau  = (const float*)d_in[4];
    const float* cent = (const float*)d_in[5];
    const float* lam  = (const float*)d_in[6];
    const int*   warm = (const int*)d_in[7];
    float* out = (float*)d_out;

    const size_t mma_smem   = (size_t)(49152 + 128) * sizeof(float);   /* 197 KB */
    const size_t exact_smem = (size_t)(16384 + 8192 + 8192 + 128 + 64) * sizeof(float);
    cudaFuncSetAttribute(k_mma,   cudaFuncAttributeMaxDynamicSharedMemorySize, (int)mma_smem);
    cudaFuncSetAttribute(k_exact, cudaFuncAttributeMaxDynamicSharedMemorySize, (int)exact_smem);

    k_qpart<<<256, 128>>>(WQ, z);
    k_qcombine<<<256, 128>>>(aw);
    k_centroid<<<256, 256>>>(cent);
    k_topc<<<64, 512>>>();
    k_clzero<<<4, 256>>>();
    k_clmask<<<64, 32>>>();
    k_mma<<<NKEYS / DN, 256, mma_smem>>>(keys);
    k_exact<<<C_CL, 256, exact_smem>>>(keys);
    k_smax_part<<<2048, 256>>>();
    k_smax_comb<<<64, 32>>>();
    k_smax_write<<<2048, 256>>>(out);
    k_refine<<<64, 256>>>(tau, lam, warm, out);
}

// round 10
// speedup vs baseline: 1.6699x; 1.0838x over previous
#include <cuda_runtime.h>
#include <math.h>
#include <float.h>
#include <stdint.h>

#define S_ASP 4
#define C_CL  1024
#define NKEYS 131072
#define DK    128
#define DA    2048
#define M_TOP 32
#define K_MAX 64
#define BB    64
#define NPC   128
#define M_CAND 4096
#define EPSF  1e-8f
#define DN    128            /* keys per MMA block */

__device__ float g_part[32 * S_ASP * DK * BB];
__device__ float g_qwT [S_ASP * DK * BB];       /* [s][k][b] for centroid kernel */
__device__ float g_qbk [S_ASP * BB * DK];       /* [s][b][k] for MMA B + exact */
__device__ float g_cscore[BB * C_CL];
__device__ int   g_topc [BB * M_TOP];
__device__ float g_sif  [(size_t)BB * NKEYS];   /* 32 MB, tf32 accuracy */
__device__ float g_refS [BB * M_CAND];          /* exact fp32 candidate scores */
__device__ unsigned long long g_clmask[C_CL];
__device__ int   g_rank [C_CL * BB];
__device__ float g_cmax [BB * 32];
__device__ float g_csum [BB * 32];
__device__ float g_rmax [BB];
__device__ float g_rsum [BB];

/* ---- warp mma tf32 m16n8k8: D += A(16x8) * B(8x8) ---- */
__device__ __forceinline__ void mma_tf32(float* c, const unsigned* a, const unsigned* b) {
    asm volatile("mma.sync.aligned.m16n8k8.row.col.f32.tf32.tf32.f32 "
                 "{%0,%1,%2,%3}, {%4,%5,%6,%7}, {%8,%9}, {%0,%1,%2,%3};"
                 : "+f"(c[0]), "+f"(c[1]), "+f"(c[2]), "+f"(c[3])
                 : "r"(a[0]), "r"(a[1]), "r"(a[2]), "r"(a[3]), "r"(b[0]), "r"(b[1]));
}
__device__ __forceinline__ unsigned smem_u32(const void* p) {
    return (unsigned)__cvta_generic_to_shared(p);
}
__device__ __forceinline__ void cpa16(unsigned d, const void* s) {
    asm volatile("cp.async.ca.shared.global [%0], [%1], 16;" :: "r"(d), "l"(s));
}
__device__ __forceinline__ void cpa_commit() { asm volatile("cp.async.commit_group;"); }
__device__ __forceinline__ void cpa_wait0()  { asm volatile("cp.async.wait_group 0;"); }

/* K1: query GEMM partials. grid 256 = s(4) x ac(32) x kh(2), 128 thr */
__global__ void __launch_bounds__(128) k_qpart(const float* __restrict__ WQ,
                                               const float* __restrict__ z) {
    int bx = blockIdx.x, s = bx >> 6, ac = (bx >> 1) & 31, kh = bx & 1;
    int a0 = ac * 64;
    __shared__ float sW[64 * 65], sZ[64 * 65];
    int tid = threadIdx.x;
    for (int idx = tid; idx < 64 * 64; idx += 128) {
        int kl = idx >> 6, aa = idx & 63;
        sW[kl * 65 + aa] = WQ[(size_t)s * DK * DA + (kh * 64 + kl) * DA + a0 + aa];
    }
    for (int idx = tid; idx < 64 * 64; idx += 128) {
        int b = idx >> 6, aa = idx & 63;
        sZ[b * 65 + aa] = z[b * DA + a0 + aa];
    }
    __syncthreads();
    int krow = tid >> 3, bcol = tid & 7;
    float acc[4][8];
#pragma unroll
    for (int i = 0; i < 4; i++)
#pragma unroll
        for (int j = 0; j < 8; j++) acc[i][j] = 0.f;
    for (int aa = 0; aa < 64; aa++) {
        float qk[4], zb[8];
#pragma unroll
        for (int i = 0; i < 4; i++) qk[i] = sW[(krow * 4 + i) * 65 + aa];
#pragma unroll
        for (int j = 0; j < 8; j++) zb[j] = sZ[(bcol * 8 + j) * 65 + aa];
#pragma unroll
        for (int i = 0; i < 4; i++)
#pragma unroll
            for (int j = 0; j < 8; j++) acc[i][j] = fmaf(qk[i], zb[j], acc[i][j]);
    }
#pragma unroll
    for (int i = 0; i < 4; i++)
#pragma unroll
        for (int j = 0; j < 8; j++)
            g_part[((ac * S_ASP + s) * DK + kh * 64 + krow * 4 + i) * BB + bcol * 8 + j] = acc[i][j];
}

/* K2: combine + l2norm + aspect softmax weight */
__global__ void __launch_bounds__(128) k_qcombine(const float* __restrict__ aw) {
    int s = blockIdx.x >> 6, b = blockIdx.x & 63, k = threadIdx.x;
    float q = 0.f;
    for (int ac = 0; ac < 32; ac++) q += g_part[((ac * S_ASP + s) * DK + k) * BB + b];
    __shared__ float red[DK];
    red[k] = q * q; __syncthreads();
    for (int off = 64; off > 0; off >>= 1) {
        if (k < off) red[k] += red[k + off];
        __syncthreads();
    }
    float rinv = 1.f / (sqrtf(red[0]) + EPSF);
    float a0 = aw[0], a1 = aw[1], a2 = aw[2], a3 = aw[3];
    float mx = fmaxf(fmaxf(a0, a1), fmaxf(a2, a3));
    float e0 = expf(a0 - mx), e1 = expf(a1 - mx), e2 = expf(a2 - mx), e3 = expf(a3 - mx);
    float ws = (s == 0 ? e0 : s == 1 ? e1 : s == 2 ? e2 : e3) / (e0 + e1 + e2 + e3);
    float v = ws * q * rinv;
    g_qwT[(s * DK + k) * BB + b] = v;
    g_qbk[(s * BB + b) * DK + k] = v;
}

/* K3: centroid scores. grid 256 (4 centroids each), 256 thr */
__global__ void __launch_bounds__(256) k_centroid(const float* __restrict__ cent) {
    int c0 = blockIdx.x * 4, tid = threadIdx.x;
    __shared__ float sc[4][S_ASP][DK];
    __shared__ float srn[4][S_ASP];
    for (int idx = tid; idx < 4 * S_ASP * DK; idx += 256) {
        int r = idx >> 7, k = idx & 127, c = r >> 2, s = r & 3;
        sc[c][s][k] = cent[((size_t)s * C_CL + c0 + c) * DK + k];
    }
    __syncthreads();
    if (tid < 16) {
        int c = tid >> 2, s = tid & 3;
        float ss = 0.f;
        for (int k = 0; k < DK; k++) { float v = sc[c][s][k]; ss += v * v; }
        srn[c][s] = 1.f / (sqrtf(ss) + EPSF);
    }
    __syncthreads();
    int c = tid >> 6, b = tid & 63;
    float acc = 0.f;
    for (int s = 0; s < S_ASP; s++) {
        float p = 0.f;
#pragma unroll 4
        for (int k = 0; k < DK; k++) p = fmaf(g_qwT[(s * DK + k) * BB + b], sc[c][s][k], p);
        acc = fmaf(p, srn[c][s], acc);
    }
    g_cscore[b * C_CL + c0 + c] = acc;
}

/* K4: top-32 of 1024 via bitonic sort of packed (score,idx). grid 64, 512 thr */
__global__ void __launch_bounds__(512) k_topc() {
    int b = blockIdx.x, tid = threadIdx.x;
    __shared__ unsigned long long key[C_CL];
#pragma unroll
    for (int r = 0; r < 2; r++) {
        int i = tid + 512 * r;
        float v = g_cscore[b * C_CL + i];
        unsigned int u = __float_as_uint(v);
        u ^= (u & 0x80000000u) ? 0xFFFFFFFFu : 0x80000000u;
        unsigned int su = ~u;
        key[i] = ((unsigned long long)su << 32) | (unsigned int)i;
    }
    __syncthreads();
    for (int size = 2; size <= C_CL; size <<= 1) {
        for (int stride = size >> 1; stride > 0; stride >>= 1) {
            int i = ((tid & ~(stride - 1)) << 1) | (tid & (stride - 1));
            int j = i + stride;
            bool up = ((i & size) == 0);
            unsigned long long a = key[i], c = key[j];
            bool sw = up ? (a > c) : (a < c);
            if (sw) { key[i] = c; key[j] = a; }
            __syncthreads();
        }
    }
    if (tid < M_TOP) g_topc[b * M_TOP + tid] = (int)(key[tid] & 0xFFFFFFFFu);
}

__global__ void __launch_bounds__(256) k_clzero() {
    int i = blockIdx.x * 256 + threadIdx.x;
    if (i < C_CL) g_clmask[i] = 0ull;
}
__global__ void __launch_bounds__(32) k_clmask() {
    int b = blockIdx.x, r = threadIdx.x;
    int c = g_topc[b * M_TOP + r];
    atomicOr(&g_clmask[c], 1ull << b);
    g_rank[c * BB + b] = r;
}

/* K5: tf32 warp-mma dense pass. grid 1024 (128 keys), 256 thr.
   cp.async.16B double-buffered tiles (no register staging -> no spills).
   smem floats: sk0 16384, sk1 16384, sq0 8192, sq1 8192, srn 128 = 197 KB.
   key tile: sk[row*128 + (k ^ 4*(row&7))]; q tile: sq[n*128 + (k ^ 4*(n&7))]. */
__global__ void __launch_bounds__(256, 1) k_mma(const float* __restrict__ keys) {
    extern __shared__ float sm[];
    float* skb[2] = {sm, sm + 16384};
    float* sqb[2] = {sm + 32768, sm + 40960};
    float* srn = sm + 49152;

    int tid = threadIdx.x, wid = tid >> 5, lane = tid & 31;
    int wm = wid & 3, wn = wid >> 2;
    int g = lane >> 2, j = lane & 3;
    int n0 = blockIdx.x * DN;

    float acc[2][4][4];
#pragma unroll
    for (int mt = 0; mt < 2; mt++)
#pragma unroll
        for (int nt = 0; nt < 4; nt++)
#pragma unroll
            for (int c = 0; c < 4; c++) acc[mt][nt][c] = 0.f;

    /* prologue: async-load s=0 into buffer 0 */
    {
        const float* kb = keys + (size_t)n0 * DK;
        unsigned kd = smem_u32(skb[0]);
#pragma unroll
        for (int i = 0; i < 16; i++) {
            int idx = tid + 256 * i;
            int row = idx >> 5, kc = (idx & 31) << 2;
            cpa16(kd + (row * DK + (kc ^ (4 * (row & 7)))) * 4, kb + (size_t)row * DK + kc);
        }
        unsigned qd = smem_u32(sqb[0]);
#pragma unroll
        for (int i = 0; i < 8; i++) {
            int idx = tid + 256 * i;
            int n = idx >> 5, kc = (idx & 31) << 2;
            cpa16(qd + (n * DK + (kc ^ (4 * (n & 7)))) * 4, g_qbk + (size_t)n * DK + kc);
        }
        cpa_commit();
        cpa_wait0();
    }
    __syncthreads();

    for (int s = 0; s < S_ASP; s++) {
        int cur = s & 1;
        float* sk = skb[cur];
        float* sq = sqb[cur];
        /* prefetch next aspect into alternate buffer (async, zero reg cost) */
        if (s < S_ASP - 1) {
            const float* kb = keys + ((size_t)(s + 1) * NKEYS + n0) * DK;
            unsigned kd = smem_u32(skb[cur ^ 1]);
#pragma unroll
            for (int i = 0; i < 16; i++) {
                int idx = tid + 256 * i;
                int row = idx >> 5, kc = (idx & 31) << 2;
                cpa16(kd + (row * DK + (kc ^ (4 * (row & 7)))) * 4, kb + (size_t)row * DK + kc);
            }
            const float* qb = g_qbk + (size_t)(s + 1) * BB * DK;
            unsigned qd = smem_u32(sqb[cur ^ 1]);
#pragma unroll
            for (int i = 0; i < 8; i++) {
                int idx = tid + 256 * i;
                int n = idx >> 5, kc = (idx & 31) << 2;
                cpa16(qd + (n * DK + (kc ^ (4 * (n & 7)))) * 4, qb + (size_t)n * DK + kc);
            }
            cpa_commit();
        }
        /* per-key inverse norms: 2 threads per row */
        {
            int row = tid >> 1, half = tid & 1;
            int sw = 4 * (row & 7);
            float ss = 0.f;
#pragma unroll
            for (int i = 0; i < 16; i++) {
                int kf = half * 64 + i * 4;
                float4 v = *(const float4*)(sk + row * DK + (kf ^ sw));
                ss += v.x * v.x + v.y * v.y + v.z * v.z + v.w * v.w;
            }
            ss += __shfl_xor_sync(0xffffffffu, ss, 1);
            if (half == 0) srn[row] = 1.f / (sqrtf(ss) + EPSF);
        }
        __syncthreads();   /* srn visible */

        float rn0[2], rn1[2];
#pragma unroll
        for (int mt = 0; mt < 2; mt++) {
            rn0[mt] = srn[wm * 32 + mt * 16 + g];
            rn1[mt] = srn[wm * 32 + mt * 16 + 8 + g];
        }
#pragma unroll
        for (int kt = 0; kt < 16; kt++) {
            int k0 = kt * 8;
            unsigned bf[4][2];
#pragma unroll
            for (int nt = 0; nt < 4; nt++) {
                int n = wn * 32 + nt * 8 + g;
                int sw = 4 * (n & 7);
                bf[nt][0] = __float_as_uint(sq[n * DK + ((k0 + j) ^ sw)]);
                bf[nt][1] = __float_as_uint(sq[n * DK + ((k0 + 4 + j) ^ sw)]);
            }
            unsigned af[2][4];
#pragma unroll
            for (int mt = 0; mt < 2; mt++) {
                int r = wm * 32 + mt * 16 + g;
                int sw = 4 * (r & 7);
                af[mt][0] = __float_as_uint(sk[r * DK + ((k0 + j) ^ sw)] * rn0[mt]);
                af[mt][1] = __float_as_uint(sk[(r + 8) * DK + ((k0 + j) ^ sw)] * rn1[mt]);
                af[mt][2] = __float_as_uint(sk[r * DK + ((k0 + 4 + j) ^ sw)] * rn0[mt]);
                af[mt][3] = __float_as_uint(sk[(r + 8) * DK + ((k0 + 4 + j) ^ sw)] * rn1[mt]);
            }
#pragma unroll
            for (int mt = 0; mt < 2; mt++)
#pragma unroll
                for (int nt = 0; nt < 4; nt++)
                    mma_tf32(acc[mt][nt], af[mt], bf[nt]);
        }
        if (s < S_ASP - 1) cpa_wait0();
        __syncthreads();   /* cur fully read; next tiles resident */
    }

    /* epilogue: c0:(key=base+g, b=2j) c1:(b+1) c2:(key+8) c3:(key+8,b+1) */
#pragma unroll
    for (int mt = 0; mt < 2; mt++) {
        int keyr = n0 + wm * 32 + mt * 16 + g;
#pragma unroll
        for (int nt = 0; nt < 4; nt++) {
            int b = wn * 32 + nt * 8 + 2 * j;
            g_sif[(size_t)b * NKEYS + keyr]           = acc[mt][nt][0];
            g_sif[(size_t)(b + 1) * NKEYS + keyr]     = acc[mt][nt][1];
            g_sif[(size_t)b * NKEYS + keyr + 8]       = acc[mt][nt][2];
            g_sif[(size_t)(b + 1) * NKEYS + keyr + 8] = acc[mt][nt][3];
        }
    }
}

/* K5b: exact fp32 candidate scores, cluster-inverted. grid 1024, 256 thr. */
__global__ void __launch_bounds__(256) k_exact(const float* __restrict__ keys) {
    extern __shared__ float es[];
    float* skey = es;                /* [key][k] at key*128 + (k ^ 4*(key&7)) */
    float* qs   = es + 16384;        /* [slot][k] */
    float* acc  = es + 16384 + 8192; /* [slot][key] */
    float* srn  = es + 16384 + 16384;
    int*   bl   = (int*)(es + 16384 + 16384 + 128);

    int c = blockIdx.x, tid = threadIdx.x;
    unsigned long long mask = g_clmask[c];
    if (mask == 0ull) return;
    int nb = __popcll(mask);
    if (tid == 0) {
        unsigned long long m = mask;
        for (int i = 0; i < nb; i++) {
            int b = __ffsll((long long)m) - 1;
            bl[i] = b;
            m &= m - 1;
        }
    }
    for (int i = tid; i < nb * DN; i += 256) acc[i] = 0.f;
    __syncthreads();

    for (int s = 0; s < S_ASP; s++) {
        const float* kb = keys + ((size_t)s * NKEYS + (size_t)c * DN) * DK;
#pragma unroll
        for (int i = 0; i < 16; i++) {
            int idx = tid + 256 * i;
            int row = idx >> 5, kc = (idx & 31) << 2;
            cpa16(smem_u32(skey + row * DK + (kc ^ (4 * (row & 7)))), kb + (size_t)row * DK + kc);
        }
        cpa_commit();
        for (int i = tid; i < nb * DK; i += 256) {
            int slot = i >> 7, k = i & 127;
            qs[i] = g_qbk[((size_t)s * BB + bl[slot]) * DK + k];
        }
        cpa_wait0();
        __syncthreads();
        {   /* norms: 2 threads per key */
            int row = tid >> 1, half = tid & 1;
            int sw = 4 * (row & 7);
            float ss = 0.f;
#pragma unroll
            for (int i = 0; i < 16; i++) {
                int kf = half * 64 + i * 4;
                float4 v = *(const float4*)(skey + row * DK + (kf ^ sw));
                ss += v.x * v.x + v.y * v.y + v.z * v.z + v.w * v.w;
            }
            ss += __shfl_xor_sync(0xffffffffu, ss, 1);
            if (half == 0) srn[row] = 1.f / (sqrtf(ss) + EPSF);
        }
        __syncthreads();
        for (int p = tid; p < nb * DN; p += 256) {
            int slot = p >> 7, key = p & 127;
            int sw = 4 * (key & 7);
            float d = 0.f;
            const float* qq = qs + slot * DK;
#pragma unroll 8
            for (int k = 0; k < DK; k++)
                d = fmaf(skey[key * DK + (k ^ sw)], qq[k], d);
            acc[p] = fmaf(d, srn[key], acc[p]);
        }
        __syncthreads();
    }
    for (int p = tid; p < nb * DN; p += 256) {
        int slot = p >> 7, key = p & 127;
        int b = bl[slot];
        int rank = g_rank[c * BB + b];
        g_refS[b * M_CAND + rank * DN + key] = acc[p];
    }
}

/* K6: per-chunk softmax stats. grid 2048 = b*32+c, 256 thr, float4 */
__global__ void __launch_bounds__(256) k_smax_part() {
    int b = blockIdx.x >> 5, c = blockIdx.x & 31, tid = threadIdx.x;
    const float4* row = (const float4*)(g_sif + (size_t)b * NKEYS + c * 4096);
    float4 v[4];
    float m = -FLT_MAX;
#pragma unroll
    for (int i = 0; i < 4; i++) {
        v[i] = row[tid + 256 * i];
        m = fmaxf(m, fmaxf(fmaxf(v[i].x, v[i].y), fmaxf(v[i].z, v[i].w)));
    }
    __shared__ float smem[256];
    smem[tid] = m; __syncthreads();
    for (int off = 128; off > 0; off >>= 1) {
        if (tid < off) smem[tid] = fmaxf(smem[tid], smem[tid + off]);
        __syncthreads();
    }
    float bm = smem[0]; __syncthreads();
    float sum = 0.f;
#pragma unroll
    for (int i = 0; i < 4; i++)
        sum += __expf(v[i].x - bm) + __expf(v[i].y - bm) + __expf(v[i].z - bm) + __expf(v[i].w - bm);
    smem[tid] = sum; __syncthreads();
    for (int off = 128; off > 0; off >>= 1) {
        if (tid < off) smem[tid] += smem[tid + off];
        __syncthreads();
    }
    if (tid == 0) { g_cmax[b * 32 + c] = bm; g_csum[b * 32 + c] = smem[0]; }
}

/* K7: combine chunk stats. grid 64, 32 thr */
__global__ void __launch_bounds__(32) k_smax_comb() {
    int b = blockIdx.x, t = threadIdx.x;
    float m = g_cmax[b * 32 + t], s = g_csum[b * 32 + t];
    float M = m;
    for (int off = 16; off > 0; off >>= 1) M = fmaxf(M, __shfl_xor_sync(0xffffffffu, M, off));
    float part = s * __expf(m - M);
    for (int off = 16; off > 0; off >>= 1) part += __shfl_xor_sync(0xffffffffu, part, off);
    if (t == 0) { g_rmax[b] = M; g_rsum[b] = part; }
}

/* K8: write soft_full. grid 2048, 256 thr, float4 */
__global__ void __launch_bounds__(256) k_smax_write(float* __restrict__ out) {
    int b = blockIdx.x >> 5, c = blockIdx.x & 31, tid = threadIdx.x;
    const float4* row = (const float4*)(g_sif + (size_t)b * NKEYS + c * 4096);
    float4* orow = (float4*)(out + 2 * BB * K_MAX + (size_t)b * NKEYS + c * 4096);
    float M = g_rmax[b], inv = 1.f / g_rsum[b];
#pragma unroll
    for (int i = 0; i < 4; i++) {
        float4 v = row[tid + 256 * i];
        orow[tid + 256 * i] = make_float4(__expf(v.x - M) * inv, __expf(v.y - M) * inv,
                                          __expf(v.z - M) * inv, __expf(v.w - M) * inv);
    }
}

/* K9: refine + top-64 + alphas. grid 64, 256 thr. Reads exact scores. */
__global__ void __launch_bounds__(256) k_refine(const float* __restrict__ taup,
                                                const float* __restrict__ lamp,
                                                const int* __restrict__ warmp,
                                                float* __restrict__ out) {
    int b = blockIdx.x, tid = threadIdx.x;
    int wid = tid >> 5, lane = tid & 31;
    __shared__ float raw[M_CAND];
    __shared__ float bvw[256];
    __shared__ float wv[8]; __shared__ int wi[8];
    __shared__ int win_i;
    __shared__ float vals[K_MAX];
    __shared__ int   gids[K_MAX];
    __shared__ float sD;
    float tau = taup[0], lam = lamp[0];
    int warm = warmp[0];

    float lsum = 0.f;
    for (int r = 0; r < 16; r++) {
        int i = tid + 256 * r;
        float si = g_refS[b * M_CAND + i];
        float v;
        if (warm) v = si;
        else {
            float g = 1.f / (1.f + expf(-lam * (si - tau)));
            v = g * expf(si);
        }
        raw[i] = v;
        lsum += v;
    }
    bvw[tid] = lsum; __syncthreads();
    for (int off = 128; off > 0; off >>= 1) {
        if (tid < off) bvw[tid] += bvw[tid + off];
        __syncthreads();
    }
    if (tid == 0) sD = bvw[0] + EPSF;
    __syncthreads();
    if (!warm) {
        float invD = 1.f / sD;
        for (int r = 0; r < 16; r++) raw[tid + 256 * r] *= invD;
    }
    __syncthreads();

    float lv = -FLT_MAX; int li = tid;
    for (int r = 0; r < 16; r++) {
        int i = tid + 256 * r;
        float v = raw[i];
        if (v > lv) { lv = v; li = i; }
    }
    for (int rr = 0; rr < K_MAX; rr++) {
        float bv = lv; int bidx = li;
#pragma unroll
        for (int off = 16; off > 0; off >>= 1) {
            float ov = __shfl_xor_sync(0xffffffffu, bv, off);
            int   oi = __shfl_xor_sync(0xffffffffu, bidx, off);
            if (ov > bv || (ov == bv && oi < bidx)) { bv = ov; bidx = oi; }
        }
        if (lane == 0) { wv[wid] = bv; wi[wid] = bidx; }
        __syncthreads();
        if (tid == 0) {
            float gbv = wv[0]; int gbi = wi[0];
            for (int w = 1; w < 8; w++) {
                if (wv[w] > gbv || (wv[w] == gbv && wi[w] < gbi)) { gbv = wv[w]; gbi = wi[w]; }
            }
            win_i = gbi;
            vals[rr] = gbv;
            gids[rr] = g_topc[b * M_TOP + (gbi >> 7)] * NPC + (gbi & 127);
        }
        __syncthreads();
        if ((win_i & 255) == tid) {
            raw[win_i] = -FLT_MAX;
            lv = -FLT_MAX; li = tid;
            for (int r = 0; r < 16; r++) {
                int i = tid + 256 * r;
                float v = raw[i];
                if (v > lv) { lv = v; li = i; }
            }
        }
        __syncthreads();
    }

    if (tid == 0) {
        float alphas[K_MAX];
        if (warm) {
            float m = -FLT_MAX;
            for (int r = 0; r < K_MAX; r++) m = fmaxf(m, vals[r]);
            float ssum = 0.f;
            for (int r = 0; r < K_MAX; r++) { alphas[r] = expf(vals[r] - m); ssum += alphas[r]; }
            float inv = 1.f / ssum;
            for (int r = 0; r < K_MAX; r++) alphas[r] *= inv;
        } else {
            float ssum = 0.f;
            for (int r = 0; r < K_MAX; r++) ssum += vals[r];
            float inv = 1.f / (ssum + EPSF);
            for (int r = 0; r < K_MAX; r++) alphas[r] = vals[r] * inv;
        }
        for (int r = 0; r < K_MAX; r++) {
            out[b * K_MAX + r] = alphas[r];
            out[BB * K_MAX + b * K_MAX + r] = (float)gids[r];
        }
    }
}

extern "C" void kernel_launch(void* const* d_in, const int* in_sizes, int n_in,
                              void* d_out, int out_size) {
    const float* z    = (const float*)d_in[0];
    const float* keys = (const float*)d_in[1];
    const float* WQ   = (const float*)d_in[2];
    const float* aw   = (const float*)d_in[3];
    const float* tau  = (const float*)d_in[4];
    const float* cent = (const float*)d_in[5];
    const float* lam  = (const float*)d_in[6];
    const int*   warm = (const int*)d_in[7];
    float* out = (float*)d_out;

    const size_t mma_smem   = (size_t)(49152 + 128) * sizeof(float);   /* 197 KB */
    const size_t exact_smem = (size_t)(16384 + 8192 + 8192 + 128 + 64) * sizeof(float);
    cudaFuncSetAttribute(k_mma,   cudaFuncAttributeMaxDynamicSharedMemorySize, (int)mma_smem);
    cudaFuncSetAttribute(k_exact, cudaFuncAttributeMaxDynamicSharedMemorySize, (int)exact_smem);

    k_qpart<<<256, 128>>>(WQ, z);
    k_qcombine<<<256, 128>>>(aw);
    k_centroid<<<256, 256>>>(cent);
    k_topc<<<64, 512>>>();
    k_clzero<<<4, 256>>>();
    k_clmask<<<64, 32>>>();
    k_mma<<<NKEYS / DN, 256, mma_smem>>>(keys);
    k_exact<<<C_CL, 256, exact_smem>>>(keys);
    k_smax_part<<<2048, 256>>>();
    k_smax_comb<<<64, 32>>>();
    k_smax_write<<<2048, 256>>>(out);
    k_refine<<<64, 256>>>(tau, lam, warm, out);
}

// round 12
// speedup vs baseline: 1.6914x; 1.0128x over previous
#include <cuda_runtime.h>
#include <math.h>
#include <float.h>
#include <stdint.h>

#define S_ASP 4
#define C_CL  1024
#define NKEYS 131072
#define DK    128
#define DA    2048
#define M_TOP 32
#define K_MAX 64
#define BB    64
#define NPC   128
#define M_CAND 4096
#define EPSF  1e-8f
#define DN    128            /* keys per MMA block == NPC */

__device__ float g_part[32 * S_ASP * DK * BB];
__device__ float g_qwT [S_ASP * DK * BB];       /* [s][k][b] for centroid kernel */
__device__ float g_qbk [S_ASP * BB * DK];       /* [s][b][k] for MMA B + exact */
__device__ float g_cscore[BB * C_CL];
__device__ int   g_topc [BB * M_TOP];
__device__ float g_sif  [(size_t)BB * NKEYS];   /* 32 MB, tf32 accuracy */
__device__ float g_refS [BB * M_CAND];          /* exact fp32 candidate scores */
__device__ unsigned long long g_clmask[C_CL];
__device__ int   g_rank [C_CL * BB];
__device__ float g_cmax [BB * 32];
__device__ float g_csum [BB * 32];
__device__ float g_rmax [BB];
__device__ float g_rsum [BB];

/* ---- warp mma tf32 m16n8k8 ---- */
__device__ __forceinline__ void mma_tf32(float* c, const unsigned* a, const unsigned* b) {
    asm volatile("mma.sync.aligned.m16n8k8.row.col.f32.tf32.tf32.f32 "
                 "{%0,%1,%2,%3}, {%4,%5,%6,%7}, {%8,%9}, {%0,%1,%2,%3};"
                 : "+f"(c[0]), "+f"(c[1]), "+f"(c[2]), "+f"(c[3])
                 : "r"(a[0]), "r"(a[1]), "r"(a[2]), "r"(a[3]), "r"(b[0]), "r"(b[1]));
}
__device__ __forceinline__ unsigned smem_u32(const void* p) {
    return (unsigned)__cvta_generic_to_shared(p);
}
__device__ __forceinline__ void cpa16(unsigned d, const void* s) {
    asm volatile("cp.async.ca.shared.global [%0], [%1], 16;" :: "r"(d), "l"(s));
}
__device__ __forceinline__ void cpa_commit() { asm volatile("cp.async.commit_group;"); }
__device__ __forceinline__ void cpa_wait0()  { asm volatile("cp.async.wait_group 0;"); }

/* K1: query GEMM partials. grid 256 = s(4) x ac(32) x kh(2), 128 thr */
__global__ void __launch_bounds__(128) k_qpart(const float* __restrict__ WQ,
                                               const float* __restrict__ z) {
    int bx = blockIdx.x, s = bx >> 6, ac = (bx >> 1) & 31, kh = bx & 1;
    int a0 = ac * 64;
    __shared__ float sW[64 * 65], sZ[64 * 65];
    int tid = threadIdx.x;
    for (int idx = tid; idx < 64 * 64; idx += 128) {
        int kl = idx >> 6, aa = idx & 63;
        sW[kl * 65 + aa] = WQ[(size_t)s * DK * DA + (kh * 64 + kl) * DA + a0 + aa];
    }
    for (int idx = tid; idx < 64 * 64; idx += 128) {
        int b = idx >> 6, aa = idx & 63;
        sZ[b * 65 + aa] = z[b * DA + a0 + aa];
    }
    __syncthreads();
    int krow = tid >> 3, bcol = tid & 7;
    float acc[4][8];
#pragma unroll
    for (int i = 0; i < 4; i++)
#pragma unroll
        for (int j = 0; j < 8; j++) acc[i][j] = 0.f;
    for (int aa = 0; aa < 64; aa++) {
        float qk[4], zb[8];
#pragma unroll
        for (int i = 0; i < 4; i++) qk[i] = sW[(krow * 4 + i) * 65 + aa];
#pragma unroll
        for (int j = 0; j < 8; j++) zb[j] = sZ[(bcol * 8 + j) * 65 + aa];
#pragma unroll
        for (int i = 0; i < 4; i++)
#pragma unroll
            for (int j = 0; j < 8; j++) acc[i][j] = fmaf(qk[i], zb[j], acc[i][j]);
    }
#pragma unroll
    for (int i = 0; i < 4; i++)
#pragma unroll
        for (int j = 0; j < 8; j++)
            g_part[((ac * S_ASP + s) * DK + kh * 64 + krow * 4 + i) * BB + bcol * 8 + j] = acc[i][j];
}

/* K2: combine + l2norm + aspect softmax weight */
__global__ void __launch_bounds__(128) k_qcombine(const float* __restrict__ aw) {
    int s = blockIdx.x >> 6, b = blockIdx.x & 63, k = threadIdx.x;
    float q = 0.f;
    for (int ac = 0; ac < 32; ac++) q += g_part[((ac * S_ASP + s) * DK + k) * BB + b];
    __shared__ float red[DK];
    red[k] = q * q; __syncthreads();
    for (int off = 64; off > 0; off >>= 1) {
        if (k < off) red[k] += red[k + off];
        __syncthreads();
    }
    float rinv = 1.f / (sqrtf(red[0]) + EPSF);
    float a0 = aw[0], a1 = aw[1], a2 = aw[2], a3 = aw[3];
    float mx = fmaxf(fmaxf(a0, a1), fmaxf(a2, a3));
    float e0 = expf(a0 - mx), e1 = expf(a1 - mx), e2 = expf(a2 - mx), e3 = expf(a3 - mx);
    float ws = (s == 0 ? e0 : s == 1 ? e1 : s == 2 ? e2 : e3) / (e0 + e1 + e2 + e3);
    float v = ws * q * rinv;
    g_qwT[(s * DK + k) * BB + b] = v;
    g_qbk[(s * BB + b) * DK + k] = v;
}

/* K3: centroid scores. grid 256 (4 centroids each), 256 thr */
__global__ void __launch_bounds__(256) k_centroid(const float* __restrict__ cent) {
    int c0 = blockIdx.x * 4, tid = threadIdx.x;
    __shared__ float sc[4][S_ASP][DK];
    __shared__ float srn[4][S_ASP];
    for (int idx = tid; idx < 4 * S_ASP * DK; idx += 256) {
        int r = idx >> 7, k = idx & 127, c = r >> 2, s = r & 3;
        sc[c][s][k] = cent[((size_t)s * C_CL + c0 + c) * DK + k];
    }
    __syncthreads();
    if (tid < 16) {
        int c = tid >> 2, s = tid & 3;
        float ss = 0.f;
        for (int k = 0; k < DK; k++) { float v = sc[c][s][k]; ss += v * v; }
        srn[c][s] = 1.f / (sqrtf(ss) + EPSF);
    }
    __syncthreads();
    int c = tid >> 6, b = tid & 63;
    float acc = 0.f;
    for (int s = 0; s < S_ASP; s++) {
        float p = 0.f;
#pragma unroll 4
        for (int k = 0; k < DK; k++) p = fmaf(g_qwT[(s * DK + k) * BB + b], sc[c][s][k], p);
        acc = fmaf(p, srn[c][s], acc);
    }
    g_cscore[b * C_CL + c0 + c] = acc;
}

/* K4: top-32 of 1024 via bitonic sort of packed (score,idx). grid 64, 512 thr */
__global__ void __launch_bounds__(512) k_topc() {
    int b = blockIdx.x, tid = threadIdx.x;
    __shared__ unsigned long long key[C_CL];
#pragma unroll
    for (int r = 0; r < 2; r++) {
        int i = tid + 512 * r;
        float v = g_cscore[b * C_CL + i];
        unsigned int u = __float_as_uint(v);
        u ^= (u & 0x80000000u) ? 0xFFFFFFFFu : 0x80000000u;
        unsigned int su = ~u;
        key[i] = ((unsigned long long)su << 32) | (unsigned int)i;
    }
    __syncthreads();
    for (int size = 2; size <= C_CL; size <<= 1) {
        for (int stride = size >> 1; stride > 0; stride >>= 1) {
            int i = ((tid & ~(stride - 1)) << 1) | (tid & (stride - 1));
            int j = i + stride;
            bool up = ((i & size) == 0);
            unsigned long long a = key[i], c = key[j];
            bool sw = up ? (a > c) : (a < c);
            if (sw) { key[i] = c; key[j] = a; }
            __syncthreads();
        }
    }
    if (tid < M_TOP) g_topc[b * M_TOP + tid] = (int)(key[tid] & 0xFFFFFFFFu);
}

__global__ void __launch_bounds__(256) k_clzero() {
    int i = blockIdx.x * 256 + threadIdx.x;
    if (i < C_CL) g_clmask[i] = 0ull;
}
__global__ void __launch_bounds__(32) k_clmask() {
    int b = blockIdx.x, r = threadIdx.x;
    int c = g_topc[b * M_TOP + r];
    atomicOr(&g_clmask[c], 1ull << b);
    g_rank[c * BB + b] = r;
}

/* K5: fused tf32 warp-mma dense pass + exact fp32 candidate scores.
   grid 1024 (block == cluster), 256 thr.
   smem floats: sk0 16384, sk1 16384, sq0 8192, sq1 8192, srn 128,
                eacc 8192, bl 64(int) = 224.8 KB -> 1 CTA/SM.
   key tile: sk[row*128 + (k ^ 4*(row&7))]; q tile: sq[n*128 + (k ^ 4*(n&7))]. */
__global__ void __launch_bounds__(256, 1) k_mma(const float* __restrict__ keys) {
    extern __shared__ float sm[];
    float* skb[2] = {sm, sm + 16384};
    float* sqb[2] = {sm + 32768, sm + 40960};
    float* srn  = sm + 49152;
    float* eacc = sm + 49280;
    int*   bl   = (int*)(sm + 49280 + 8192);

    int tid = threadIdx.x, wid = tid >> 5, lane = tid & 31;
    int wm = wid & 3, wn = wid >> 2;
    int g = lane >> 2, j = lane & 3;
    int n0 = blockIdx.x * DN;

    /* candidate-batch list for this cluster */
    unsigned long long mask = g_clmask[blockIdx.x];
    int nb = __popcll(mask);
    if (tid == 0) {
        unsigned long long m = mask;
        for (int i = 0; i < nb; i++) {
            bl[i] = __ffsll((long long)m) - 1;
            m &= m - 1;
        }
    }
    for (int i = tid; i < nb * DN; i += 256) eacc[i] = 0.f;

    float acc[2][4][4];
#pragma unroll
    for (int mt = 0; mt < 2; mt++)
#pragma unroll
        for (int nt = 0; nt < 4; nt++)
#pragma unroll
            for (int c = 0; c < 4; c++) acc[mt][nt][c] = 0.f;

    /* prologue: async-load s=0 into buffer 0 */
    {
        const float* kb = keys + (size_t)n0 * DK;
        unsigned kd = smem_u32(skb[0]);
#pragma unroll
        for (int i = 0; i < 16; i++) {
            int idx = tid + 256 * i;
            int row = idx >> 5, kc = (idx & 31) << 2;
            cpa16(kd + (row * DK + (kc ^ (4 * (row & 7)))) * 4, kb + (size_t)row * DK + kc);
        }
        unsigned qd = smem_u32(sqb[0]);
#pragma unroll
        for (int i = 0; i < 8; i++) {
            int idx = tid + 256 * i;
            int n = idx >> 5, kc = (idx & 31) << 2;
            cpa16(qd + (n * DK + (kc ^ (4 * (n & 7)))) * 4, g_qbk + (size_t)n * DK + kc);
        }
        cpa_commit();
        cpa_wait0();
    }
    __syncthreads();

    for (int s = 0; s < S_ASP; s++) {
        int cur = s & 1;
        float* sk = skb[cur];
        float* sq = sqb[cur];
        /* prefetch next aspect into alternate buffer */
        if (s < S_ASP - 1) {
            const float* kb = keys + ((size_t)(s + 1) * NKEYS + n0) * DK;
            unsigned kd = smem_u32(skb[cur ^ 1]);
#pragma unroll
            for (int i = 0; i < 16; i++) {
                int idx = tid + 256 * i;
                int row = idx >> 5, kc = (idx & 31) << 2;
                cpa16(kd + (row * DK + (kc ^ (4 * (row & 7)))) * 4, kb + (size_t)row * DK + kc);
            }
            const float* qb = g_qbk + (size_t)(s + 1) * BB * DK;
            unsigned qd = smem_u32(sqb[cur ^ 1]);
#pragma unroll
            for (int i = 0; i < 8; i++) {
                int idx = tid + 256 * i;
                int n = idx >> 5, kc = (idx & 31) << 2;
                cpa16(qd + (n * DK + (kc ^ (4 * (n & 7)))) * 4, qb + (size_t)n * DK + kc);
            }
            cpa_commit();
        }
        /* per-key inverse norms: 2 threads per row */
        {
            int row = tid >> 1, half = tid & 1;
            int sw = 4 * (row & 7);
            float ss = 0.f;
#pragma unroll
            for (int i = 0; i < 16; i++) {
                int kf = half * 64 + i * 4;
                float4 v = *(const float4*)(sk + row * DK + (kf ^ sw));
                ss += v.x * v.x + v.y * v.y + v.z * v.z + v.w * v.w;
            }
            ss += __shfl_xor_sync(0xffffffffu, ss, 1);
            if (half == 0) srn[row] = 1.f / (sqrtf(ss) + EPSF);
        }
        __syncthreads();   /* srn visible */

        float rn0[2], rn1[2];
#pragma unroll
        for (int mt = 0; mt < 2; mt++) {
            rn0[mt] = srn[wm * 32 + mt * 16 + g];
            rn1[mt] = srn[wm * 32 + mt * 16 + 8 + g];
        }
#pragma unroll
        for (int kt = 0; kt < 16; kt++) {
            int k0 = kt * 8;
            unsigned bf[4][2];
#pragma unroll
            for (int nt = 0; nt < 4; nt++) {
                int n = wn * 32 + nt * 8 + g;
                int sw = 4 * (n & 7);
                bf[nt][0] = __float_as_uint(sq[n * DK + ((k0 + j) ^ sw)]);
                bf[nt][1] = __float_as_uint(sq[n * DK + ((k0 + 4 + j) ^ sw)]);
            }
            unsigned af[2][4];
#pragma unroll
            for (int mt = 0; mt < 2; mt++) {
                int r = wm * 32 + mt * 16 + g;
                int sw = 4 * (r & 7);
                af[mt][0] = __float_as_uint(sk[r * DK + ((k0 + j) ^ sw)] * rn0[mt]);
                af[mt][1] = __float_as_uint(sk[(r + 8) * DK + ((k0 + j) ^ sw)] * rn1[mt]);
                af[mt][2] = __float_as_uint(sk[r * DK + ((k0 + 4 + j) ^ sw)] * rn0[mt]);
                af[mt][3] = __float_as_uint(sk[(r + 8) * DK + ((k0 + 4 + j) ^ sw)] * rn1[mt]);
            }
#pragma unroll
            for (int mt = 0; mt < 2; mt++)
#pragma unroll
                for (int nt = 0; nt < 4; nt++)
                    mma_tf32(acc[mt][nt], af[mt], bf[nt]);
        }
        /* exact fp32 candidate dots for this cluster, this aspect */
        for (int p = tid; p < nb * DN; p += 256) {
            int slot = p >> 7, keyr = p & 127;
            int b = bl[slot];
            int swk = 4 * (keyr & 7), swq = 4 * (b & 7);
            const float* kr = sk + keyr * DK;
            const float* qr = sq + b * DK;
            float d = 0.f;
#pragma unroll 8
            for (int k = 0; k < DK; k++)
                d = fmaf(kr[k ^ swk], qr[k ^ swq], d);
            eacc[p] = fmaf(d, srn[keyr], eacc[p]);
        }
        if (s < S_ASP - 1) cpa_wait0();
        __syncthreads();   /* cur fully read; next tiles resident */
    }

    /* exact writeout */
    for (int p = tid; p < nb * DN; p += 256) {
        int slot = p >> 7, keyr = p & 127;
        int b = bl[slot];
        int rank = g_rank[blockIdx.x * BB + b];
        g_refS[b * M_CAND + rank * DN + keyr] = eacc[p];
    }

    /* epilogue: stage accs to smem (132-pad rows), then coalesced float4 writes */
    float* so = skb[0];   /* free: last aspect used skb[1] */
#pragma unroll
    for (int mt = 0; mt < 2; mt++) {
        int kl0 = wm * 32 + mt * 16 + g;
#pragma unroll
        for (int nt = 0; nt < 4; nt++) {
            int b = wn * 32 + nt * 8 + 2 * j;
            so[b * 132 + kl0]             = acc[mt][nt][0];
            so[(b + 1) * 132 + kl0]       = acc[mt][nt][1];
            so[b * 132 + kl0 + 8]         = acc[mt][nt][2];
            so[(b + 1) * 132 + kl0 + 8]   = acc[mt][nt][3];
        }
    }
    __syncthreads();
#pragma unroll
    for (int i = 0; i < 8; i++) {
        int idx = tid + 256 * i;          /* 2048 float4 total */
        int b = idx >> 5, q4 = (idx & 31) << 2;
        float4 v = *(const float4*)(so + b * 132 + q4);
        *(float4*)(g_sif + (size_t)b * NKEYS + n0 + q4) = v;
    }
}

/* K6: per-chunk softmax stats. grid 2048 = b*32+c, 256 thr, float4 */
__global__ void __launch_bounds__(256) k_smax_part() {
    int b = blockIdx.x >> 5, c = blockIdx.x & 31, tid = threadIdx.x;
    const float4* row = (const float4*)(g_sif + (size_t)b * NKEYS + c * 4096);
    float4 v[4];
    float m = -FLT_MAX;
#pragma unroll
    for (int i = 0; i < 4; i++) {
        v[i] = row[tid + 256 * i];
        m = fmaxf(m, fmaxf(fmaxf(v[i].x, v[i].y), fmaxf(v[i].z, v[i].w)));
    }
    __shared__ float smem[256];
    smem[tid] = m; __syncthreads();
    for (int off = 128; off > 0; off >>= 1) {
        if (tid < off) smem[tid] = fmaxf(smem[tid], smem[tid + off]);
        __syncthreads();
    }
    float bm = smem[0]; __syncthreads();
    float sum = 0.f;
#pragma unroll
    for (int i = 0; i < 4; i++)
        sum += __expf(v[i].x - bm) + __expf(v[i].y - bm) + __expf(v[i].z - bm) + __expf(v[i].w - bm);
    smem[tid] = sum; __syncthreads();
    for (int off = 128; off > 0; off >>= 1) {
        if (tid < off) smem[tid] += smem[tid + off];
        __syncthreads();
    }
    if (tid == 0) { g_cmax[b * 32 + c] = bm; g_csum[b * 32 + c] = smem[0]; }
}

/* K7: combine chunk stats. grid 64, 32 thr */
__global__ void __launch_bounds__(32) k_smax_comb() {
    int b = blockIdx.x, t = threadIdx.x;
    float m = g_cmax[b * 32 + t], s = g_csum[b * 32 + t];
    float M = m;
    for (int off = 16; off > 0; off >>= 1) M = fmaxf(M, __shfl_xor_sync(0xffffffffu, M, off));
    float part = s * __expf(m - M);
    for (int off = 16; off > 0; off >>= 1) part += __shfl_xor_sync(0xffffffffu, part, off);
    if (t == 0) { g_rmax[b] = M; g_rsum[b] = part; }
}

/* K8: write soft_full. grid 2048, 256 thr, float4 */
__global__ void __launch_bounds__(256) k_smax_write(float* __restrict__ out) {
    int b = blockIdx.x >> 5, c = blockIdx.x & 31, tid = threadIdx.x;
    const float4* row = (const float4*)(g_sif + (size_t)b * NKEYS + c * 4096);
    float4* orow = (float4*)(out + 2 * BB * K_MAX + (size_t)b * NKEYS + c * 4096);
    float M = g_rmax[b], inv = 1.f / g_rsum[b];
#pragma unroll
    for (int i = 0; i < 4; i++) {
        float4 v = row[tid + 256 * i];
        orow[tid + 256 * i] = make_float4(__expf(v.x - M) * inv, __expf(v.y - M) * inv,
                                          __expf(v.z - M) * inv, __expf(v.w - M) * inv);
    }
}

/* K9: refine + top-64 + alphas. grid 64, 256 thr. Reads exact scores. */
__global__ void __launch_bounds__(256) k_refine(const float* __restrict__ taup,
                                                const float* __restrict__ lamp,
                                                const int* __restrict__ warmp,
                                                float* __restrict__ out) {
    int b = blockIdx.x, tid = threadIdx.x;
    int wid = tid >> 5, lane = tid & 31;
    __shared__ float raw[M_CAND];
    __shared__ float bvw[256];
    __shared__ float wv[8]; __shared__ int wi[8];
    __shared__ int win_i;
    __shared__ float vals[K_MAX];
    __shared__ int   gids[K_MAX];
    __shared__ float sD;
    float tau = taup[0], lam = lamp[0];
    int warm = warmp[0];

    float lsum = 0.f;
    for (int r = 0; r < 16; r++) {
        int i = tid + 256 * r;
        float si = g_refS[b * M_CAND + i];
        float v;
        if (warm) v = si;
        else {
            float g = 1.f / (1.f + expf(-lam * (si - tau)));
            v = g * expf(si);
        }
        raw[i] = v;
        lsum += v;
    }
    bvw[tid] = lsum; __syncthreads();
    for (int off = 128; off > 0; off >>= 1) {
        if (tid < off) bvw[tid] += bvw[tid + off];
        __syncthreads();
    }
    if (tid == 0) sD = bvw[0] + EPSF;
    __syncthreads();
    if (!warm) {
        float invD = 1.f / sD;
        for (int r = 0; r < 16; r++) raw[tid + 256 * r] *= invD;
    }
    __syncthreads();

    float lv = -FLT_MAX; int li = tid;
    for (int r = 0; r < 16; r++) {
        int i = tid + 256 * r;
        float v = raw[i];
        if (v > lv) { lv = v; li = i; }
    }
    for (int rr = 0; rr < K_MAX; rr++) {
        float bv = lv; int bidx = li;
#pragma unroll
        for (int off = 16; off > 0; off >>= 1) {
            float ov = __shfl_xor_sync(0xffffffffu, bv, off);
            int   oi = __shfl_xor_sync(0xffffffffu, bidx, off);
            if (ov > bv || (ov == bv && oi < bidx)) { bv = ov; bidx = oi; }
        }
        if (lane == 0) { wv[wid] = bv; wi[wid] = bidx; }
        __syncthreads();
        if (tid == 0) {
            float gbv = wv[0]; int gbi = wi[0];
            for (int w = 1; w < 8; w++) {
                if (wv[w] > gbv || (wv[w] == gbv && wi[w] < gbi)) { gbv = wv[w]; gbi = wi[w]; }
            }
            win_i = gbi;
            vals[rr] = gbv;
            gids[rr] = g_topc[b * M_TOP + (gbi >> 7)] * NPC + (gbi & 127);
        }
        __syncthreads();
        if ((win_i & 255) == tid) {
            raw[win_i] = -FLT_MAX;
            lv = -FLT_MAX; li = tid;
            for (int r = 0; r < 16; r++) {
                int i = tid + 256 * r;
                float v = raw[i];
                if (v > lv) { lv = v; li = i; }
            }
        }
        __syncthreads();
    }

    if (tid == 0) {
        float alphas[K_MAX];
        if (warm) {
            float m = -FLT_MAX;
            for (int r = 0; r < K_MAX; r++) m = fmaxf(m, vals[r]);
            float ssum = 0.f;
            for (int r = 0; r < K_MAX; r++) { alphas[r] = expf(vals[r] - m); ssum += alphas[r]; }
            float inv = 1.f / ssum;
            for (int r = 0; r < K_MAX; r++) alphas[r] *= inv;
        } else {
            float ssum = 0.f;
            for (int r = 0; r < K_MAX; r++) ssum += vals[r];
            float inv = 1.f / (ssum + EPSF);
            for (int r = 0; r < K_MAX; r++) alphas[r] = vals[r] * inv;
        }
        for (int r = 0; r < K_MAX; r++) {
            out[b * K_MAX + r] = alphas[r];
            out[BB * K_MAX + b * K_MAX + r] = (float)gids[r];
        }
    }
}

extern "C" void kernel_launch(void* const* d_in, const int* in_sizes, int n_in,
                              void* d_out, int out_size) {
    const float* z    = (const float*)d_in[0];
    const float* keys = (const float*)d_in[1];
    const float* WQ   = (const float*)d_in[2];
    const float* aw   = (const float*)d_in[3];
    const float* tau  = (const float*)d_in[4];
    const float* cent = (const float*)d_in[5];
    const float* lam  = (const float*)d_in[6];
    const int*   warm = (const int*)d_in[7];
    float* out = (float*)d_out;

    const size_t mma_smem = (size_t)(49280 + 8192 + 64) * sizeof(float);  /* 224.8 KB */
    cudaFuncSetAttribute(k_mma, cudaFuncAttributeMaxDynamicSharedMemorySize, (int)mma_smem);

    k_clzero<<<4, 256>>>();
    k_qpart<<<256, 128>>>(WQ, z);
    k_qcombine<<<256, 128>>>(aw);
    k_centroid<<<256, 256>>>(cent);
    k_topc<<<64, 512>>>();
    k_clmask<<<64, 32>>>();
    k_mma<<<NKEYS / DN, 256, mma_smem>>>(keys);
    k_smax_part<<<2048, 256>>>();
    k_smax_comb<<<64, 32>>>();
    k_smax_write<<<2048, 256>>>(out);
    k_refine<<<64, 256>>>(tau, lam, warm, out);
}

// round 13
// speedup vs baseline: 1.8020x; 1.0654x over previous
#include <cuda_runtime.h>
#include <math.h>
#include <float.h>
#include <stdint.h>

#define S_ASP 4
#define C_CL  1024
#define NKEYS 131072
#define DK    128
#define DA    2048
#define M_TOP 32
#define K_MAX 64
#define BB    64
#define NPC   128
#define M_CAND 4096
#define EPSF  1e-8f
#define DN    128            /* keys per MMA block == NPC */

__device__ float g_part[32 * S_ASP * DK * BB];
__device__ float g_qwT [S_ASP * DK * BB];       /* [s][k][b] */
__device__ float g_qbk [S_ASP * BB * DK];       /* [s][b][k] */
__device__ float g_cscore[BB * C_CL];
__device__ int   g_topc [BB * M_TOP];
__device__ float g_sif  [(size_t)BB * NKEYS];   /* 32 MB, tf32 accuracy */
__device__ float g_refS [BB * M_CAND];          /* exact fp32 candidate scores */
__device__ unsigned long long g_clmask[C_CL];
__device__ int   g_rank [C_CL * BB];
__device__ float g_cmax [BB * 32];
__device__ float g_csum [BB * 32];
__device__ float g_rmax [BB];
__device__ float g_rsum [BB];

/* ---- warp mma tf32 m16n8k8 ---- */
__device__ __forceinline__ void mma_tf32(float* c, const unsigned* a, const unsigned* b) {
    asm volatile("mma.sync.aligned.m16n8k8.row.col.f32.tf32.tf32.f32 "
                 "{%0,%1,%2,%3}, {%4,%5,%6,%7}, {%8,%9}, {%0,%1,%2,%3};"
                 : "+f"(c[0]), "+f"(c[1]), "+f"(c[2]), "+f"(c[3])
                 : "r"(a[0]), "r"(a[1]), "r"(a[2]), "r"(a[3]), "r"(b[0]), "r"(b[1]));
}
__device__ __forceinline__ unsigned smem_u32(const void* p) {
    return (unsigned)__cvta_generic_to_shared(p);
}
__device__ __forceinline__ void cpa16(unsigned d, const void* s) {
    asm volatile("cp.async.ca.shared.global [%0], [%1], 16;" :: "r"(d), "l"(s));
}
__device__ __forceinline__ void cpa_commit() { asm volatile("cp.async.commit_group;"); }
__device__ __forceinline__ void cpa_wait0()  { asm volatile("cp.async.wait_group 0;"); }

/* K1: query GEMM partials. grid 256 = s(4) x ac(32) x kh(2), 128 thr */
__global__ void __launch_bounds__(128) k_qpart(const float* __restrict__ WQ,
                                               const float* __restrict__ z) {
    int bx = blockIdx.x, s = bx >> 6, ac = (bx >> 1) & 31, kh = bx & 1;
    int a0 = ac * 64;
    __shared__ float sW[64 * 65], sZ[64 * 65];
    int tid = threadIdx.x;
    for (int idx = tid; idx < 64 * 64; idx += 128) {
        int kl = idx >> 6, aa = idx & 63;
        sW[kl * 65 + aa] = WQ[(size_t)s * DK * DA + (kh * 64 + kl) * DA + a0 + aa];
    }
    for (int idx = tid; idx < 64 * 64; idx += 128) {
        int b = idx >> 6, aa = idx & 63;
        sZ[b * 65 + aa] = z[b * DA + a0 + aa];
    }
    __syncthreads();
    int krow = tid >> 3, bcol = tid & 7;
    float acc[4][8];
#pragma unroll
    for (int i = 0; i < 4; i++)
#pragma unroll
        for (int j = 0; j < 8; j++) acc[i][j] = 0.f;
    for (int aa = 0; aa < 64; aa++) {
        float qk[4], zb[8];
#pragma unroll
        for (int i = 0; i < 4; i++) qk[i] = sW[(krow * 4 + i) * 65 + aa];
#pragma unroll
        for (int j = 0; j < 8; j++) zb[j] = sZ[(bcol * 8 + j) * 65 + aa];
#pragma unroll
        for (int i = 0; i < 4; i++)
#pragma unroll
            for (int j = 0; j < 8; j++) acc[i][j] = fmaf(qk[i], zb[j], acc[i][j]);
    }
#pragma unroll
    for (int i = 0; i < 4; i++)
#pragma unroll
        for (int j = 0; j < 8; j++)
            g_part[((ac * S_ASP + s) * DK + kh * 64 + krow * 4 + i) * BB + bcol * 8 + j] = acc[i][j];
}

/* K2: combine + l2norm + aspect softmax weight */
__global__ void __launch_bounds__(128) k_qcombine(const float* __restrict__ aw) {
    int s = blockIdx.x >> 6, b = blockIdx.x & 63, k = threadIdx.x;
    float q = 0.f;
    for (int ac = 0; ac < 32; ac++) q += g_part[((ac * S_ASP + s) * DK + k) * BB + b];
    __shared__ float red[DK];
    red[k] = q * q; __syncthreads();
    for (int off = 64; off > 0; off >>= 1) {
        if (k < off) red[k] += red[k + off];
        __syncthreads();
    }
    float rinv = 1.f / (sqrtf(red[0]) + EPSF);
    float a0 = aw[0], a1 = aw[1], a2 = aw[2], a3 = aw[3];
    float mx = fmaxf(fmaxf(a0, a1), fmaxf(a2, a3));
    float e0 = expf(a0 - mx), e1 = expf(a1 - mx), e2 = expf(a2 - mx), e3 = expf(a3 - mx);
    float ws = (s == 0 ? e0 : s == 1 ? e1 : s == 2 ? e2 : e3) / (e0 + e1 + e2 + e3);
    float v = ws * q * rinv;
    g_qwT[(s * DK + k) * BB + b] = v;
    g_qbk[(s * BB + b) * DK + k] = v;
}

/* K3: centroid scores, smem-cached. grid 64 (16 centroids each), 512 thr.
   dyn smem floats: sqw 32768 (full g_qwT) + scn 8192 (16 rows x 512) + srn 64
   = 160.25 KB. All dot products from smem (qw conflict-free, scn broadcast). */
__global__ void __launch_bounds__(512) k_centroid(const float* __restrict__ cent) {
    extern __shared__ float cs[];
    float* sqw = cs;            /* [s*128+k][b] */
    float* scn = cs + 32768;    /* [ci][s*128+k] */
    float* srn = cs + 40960;    /* [ci*4+s] */
    int tid = threadIdx.x;
    int c0 = blockIdx.x * 16;

    {   /* full qwT copy, coalesced */
        const float4* src = (const float4*)g_qwT;
        float4* dst = (float4*)sqw;
#pragma unroll
        for (int i = 0; i < 16; i++) dst[tid + 512 * i] = src[tid + 512 * i];
    }
    {   /* 16 centroid rows x 4 aspects x 128 k */
#pragma unroll
        for (int ii = 0; ii < 4; ii++) {
            int i = tid + 512 * ii;          /* 2048 float4 */
            int ci = i >> 7;                 /* 128 float4 per (ci) row of 512 floats */
            int r = i & 127;
            int s = r >> 5, k4 = (r & 31) << 2;
            ((float4*)scn)[i] = *(const float4*)(cent + ((size_t)s * C_CL + c0 + ci) * DK + k4);
        }
    }
    __syncthreads();
    if (tid < 64) {
        int ci = tid >> 2, s = tid & 3;
        const float* row = scn + ci * 512 + s * DK;
        float ss = 0.f;
#pragma unroll
        for (int k = 0; k < DK; k += 4) {
            float4 v = *(const float4*)(row + k);
            ss += v.x * v.x + v.y * v.y + v.z * v.z + v.w * v.w;
        }
        srn[tid] = 1.f / (sqrtf(ss) + EPSF);
    }
    __syncthreads();
#pragma unroll
    for (int it = 0; it < 2; it++) {
        int i = tid + 512 * it;              /* 1024 items: ci x b */
        int ci = i >> 6, b = i & 63;
        float acc = 0.f;
#pragma unroll
        for (int s = 0; s < S_ASP; s++) {
            const float* qw = sqw + s * DK * BB + b;
            const float* cr = scn + ci * 512 + s * DK;
            float p = 0.f;
#pragma unroll 8
            for (int k = 0; k < DK; k++) p = fmaf(qw[k * BB], cr[k], p);
            acc = fmaf(p, srn[ci * 4 + s], acc);
        }
        g_cscore[b * C_CL + c0 + ci] = acc;
    }
}

/* K4: top-32 of 1024 via bitonic sort; also zeroes this block's clmask slice. */
__global__ void __launch_bounds__(512) k_topc() {
    int b = blockIdx.x, tid = threadIdx.x;
    __shared__ unsigned long long key[C_CL];
    if (tid < 16) g_clmask[b * 16 + tid] = 0ull;   /* 64 blocks x 16 = C_CL */
#pragma unroll
    for (int r = 0; r < 2; r++) {
        int i = tid + 512 * r;
        float v = g_cscore[b * C_CL + i];
        unsigned int u = __float_as_uint(v);
        u ^= (u & 0x80000000u) ? 0xFFFFFFFFu : 0x80000000u;
        unsigned int su = ~u;
        key[i] = ((unsigned long long)su << 32) | (unsigned int)i;
    }
    __syncthreads();
    for (int size = 2; size <= C_CL; size <<= 1) {
        for (int stride = size >> 1; stride > 0; stride >>= 1) {
            int i = ((tid & ~(stride - 1)) << 1) | (tid & (stride - 1));
            int j = i + stride;
            bool up = ((i & size) == 0);
            unsigned long long a = key[i], c = key[j];
            bool sw = up ? (a > c) : (a < c);
            if (sw) { key[i] = c; key[j] = a; }
            __syncthreads();
        }
    }
    if (tid < M_TOP) g_topc[b * M_TOP + tid] = (int)(key[tid] & 0xFFFFFFFFu);
}

__global__ void __launch_bounds__(32) k_clmask() {
    int b = blockIdx.x, r = threadIdx.x;
    int c = g_topc[b * M_TOP + r];
    atomicOr(&g_clmask[c], 1ull << b);
    g_rank[c * BB + b] = r;
}

/* K5: fused tf32 warp-mma dense pass + exact fp32 candidate scores.
   grid 1024 (block == cluster), 256 thr. smem 224.8 KB -> 1 CTA/SM. */
__global__ void __launch_bounds__(256, 1) k_mma(const float* __restrict__ keys) {
    extern __shared__ float sm[];
    float* skb[2] = {sm, sm + 16384};
    float* sqb[2] = {sm + 32768, sm + 40960};
    float* srn  = sm + 49152;
    float* eacc = sm + 49280;
    int*   bl   = (int*)(sm + 49280 + 8192);

    int tid = threadIdx.x, wid = tid >> 5, lane = tid & 31;
    int wm = wid & 3, wn = wid >> 2;
    int g = lane >> 2, j = lane & 3;
    int n0 = blockIdx.x * DN;

    unsigned long long mask = g_clmask[blockIdx.x];
    int nb = __popcll(mask);
    if (tid == 0) {
        unsigned long long m = mask;
        for (int i = 0; i < nb; i++) {
            bl[i] = __ffsll((long long)m) - 1;
            m &= m - 1;
        }
    }
    for (int i = tid; i < nb * DN; i += 256) eacc[i] = 0.f;

    float acc[2][4][4];
#pragma unroll
    for (int mt = 0; mt < 2; mt++)
#pragma unroll
        for (int nt = 0; nt < 4; nt++)
#pragma unroll
            for (int c = 0; c < 4; c++) acc[mt][nt][c] = 0.f;

    {   /* prologue: async-load s=0 into buffer 0 */
        const float* kb = keys + (size_t)n0 * DK;
        unsigned kd = smem_u32(skb[0]);
#pragma unroll
        for (int i = 0; i < 16; i++) {
            int idx = tid + 256 * i;
            int row = idx >> 5, kc = (idx & 31) << 2;
            cpa16(kd + (row * DK + (kc ^ (4 * (row & 7)))) * 4, kb + (size_t)row * DK + kc);
        }
        unsigned qd = smem_u32(sqb[0]);
#pragma unroll
        for (int i = 0; i < 8; i++) {
            int idx = tid + 256 * i;
            int n = idx >> 5, kc = (idx & 31) << 2;
            cpa16(qd + (n * DK + (kc ^ (4 * (n & 7)))) * 4, g_qbk + (size_t)n * DK + kc);
        }
        cpa_commit();
        cpa_wait0();
    }
    __syncthreads();

    for (int s = 0; s < S_ASP; s++) {
        int cur = s & 1;
        float* sk = skb[cur];
        float* sq = sqb[cur];
        if (s < S_ASP - 1) {
            const float* kb = keys + ((size_t)(s + 1) * NKEYS + n0) * DK;
            unsigned kd = smem_u32(skb[cur ^ 1]);
#pragma unroll
            for (int i = 0; i < 16; i++) {
                int idx = tid + 256 * i;
                int row = idx >> 5, kc = (idx & 31) << 2;
                cpa16(kd + (row * DK + (kc ^ (4 * (row & 7)))) * 4, kb + (size_t)row * DK + kc);
            }
            const float* qb = g_qbk + (size_t)(s + 1) * BB * DK;
            unsigned qd = smem_u32(sqb[cur ^ 1]);
#pragma unroll
            for (int i = 0; i < 8; i++) {
                int idx = tid + 256 * i;
                int n = idx >> 5, kc = (idx & 31) << 2;
                cpa16(qd + (n * DK + (kc ^ (4 * (n & 7)))) * 4, qb + (size_t)n * DK + kc);
            }
            cpa_commit();
        }
        {   /* per-key inverse norms: 2 threads per row */
            int row = tid >> 1, half = tid & 1;
            int sw = 4 * (row & 7);
            float ss = 0.f;
#pragma unroll
            for (int i = 0; i < 16; i++) {
                int kf = half * 64 + i * 4;
                float4 v = *(const float4*)(sk + row * DK + (kf ^ sw));
                ss += v.x * v.x + v.y * v.y + v.z * v.z + v.w * v.w;
            }
            ss += __shfl_xor_sync(0xffffffffu, ss, 1);
            if (half == 0) srn[row] = 1.f / (sqrtf(ss) + EPSF);
        }
        __syncthreads();

        float rn0[2], rn1[2];
#pragma unroll
        for (int mt = 0; mt < 2; mt++) {
            rn0[mt] = srn[wm * 32 + mt * 16 + g];
            rn1[mt] = srn[wm * 32 + mt * 16 + 8 + g];
        }
#pragma unroll
        for (int kt = 0; kt < 16; kt++) {
            int k0 = kt * 8;
            unsigned bf[4][2];
#pragma unroll
            for (int nt = 0; nt < 4; nt++) {
                int n = wn * 32 + nt * 8 + g;
                int sw = 4 * (n & 7);
                bf[nt][0] = __float_as_uint(sq[n * DK + ((k0 + j) ^ sw)]);
                bf[nt][1] = __float_as_uint(sq[n * DK + ((k0 + 4 + j) ^ sw)]);
            }
            unsigned af[2][4];
#pragma unroll
            for (int mt = 0; mt < 2; mt++) {
                int r = wm * 32 + mt * 16 + g;
                int sw = 4 * (r & 7);
                af[mt][0] = __float_as_uint(sk[r * DK + ((k0 + j) ^ sw)] * rn0[mt]);
                af[mt][1] = __float_as_uint(sk[(r + 8) * DK + ((k0 + j) ^ sw)] * rn1[mt]);
                af[mt][2] = __float_as_uint(sk[r * DK + ((k0 + 4 + j) ^ sw)] * rn0[mt]);
                af[mt][3] = __float_as_uint(sk[(r + 8) * DK + ((k0 + 4 + j) ^ sw)] * rn1[mt]);
            }
#pragma unroll
            for (int mt = 0; mt < 2; mt++)
#pragma unroll
                for (int nt = 0; nt < 4; nt++)
                    mma_tf32(acc[mt][nt], af[mt], bf[nt]);
        }
        /* exact fp32 candidate dots for this cluster, this aspect */
        for (int p = tid; p < nb * DN; p += 256) {
            int slot = p >> 7, keyr = p & 127;
            int b = bl[slot];
            int swk = 4 * (keyr & 7), swq = 4 * (b & 7);
            const float* kr = sk + keyr * DK;
            const float* qr = sq + b * DK;
            float d = 0.f;
#pragma unroll 8
            for (int k = 0; k < DK; k++)
                d = fmaf(kr[k ^ swk], qr[k ^ swq], d);
            eacc[p] = fmaf(d, srn[keyr], eacc[p]);
        }
        if (s < S_ASP - 1) cpa_wait0();
        __syncthreads();
    }

    /* exact writeout */
    for (int p = tid; p < nb * DN; p += 256) {
        int slot = p >> 7, keyr = p & 127;
        int b = bl[slot];
        int rank = g_rank[blockIdx.x * BB + b];
        g_refS[b * M_CAND + rank * DN + keyr] = eacc[p];
    }

    /* epilogue: stage accs to smem (132-pad rows), then coalesced float4 writes */
    float* so = skb[0];
#pragma unroll
    for (int mt = 0; mt < 2; mt++) {
        int kl0 = wm * 32 + mt * 16 + g;
#pragma unroll
        for (int nt = 0; nt < 4; nt++) {
            int b = wn * 32 + nt * 8 + 2 * j;
            so[b * 132 + kl0]             = acc[mt][nt][0];
            so[(b + 1) * 132 + kl0]       = acc[mt][nt][1];
            so[b * 132 + kl0 + 8]         = acc[mt][nt][2];
            so[(b + 1) * 132 + kl0 + 8]   = acc[mt][nt][3];
        }
    }
    __syncthreads();
#pragma unroll
    for (int i = 0; i < 8; i++) {
        int idx = tid + 256 * i;
        int b = idx >> 5, q4 = (idx & 31) << 2;
        float4 v = *(const float4*)(so + b * 132 + q4);
        *(float4*)(g_sif + (size_t)b * NKEYS + n0 + q4) = v;
    }
}

/* K6: per-chunk softmax stats. grid 2048 = b*32+c, 256 thr, float4 */
__global__ void __launch_bounds__(256) k_smax_part() {
    int b = blockIdx.x >> 5, c = blockIdx.x & 31, tid = threadIdx.x;
    const float4* row = (const float4*)(g_sif + (size_t)b * NKEYS + c * 4096);
    float4 v[4];
    float m = -FLT_MAX;
#pragma unroll
    for (int i = 0; i < 4; i++) {
        v[i] = row[tid + 256 * i];
        m = fmaxf(m, fmaxf(fmaxf(v[i].x, v[i].y), fmaxf(v[i].z, v[i].w)));
    }
    __shared__ float smem[256];
    smem[tid] = m; __syncthreads();
    for (int off = 128; off > 0; off >>= 1) {
        if (tid < off) smem[tid] = fmaxf(smem[tid], smem[tid + off]);
        __syncthreads();
    }
    float bm = smem[0]; __syncthreads();
    float sum = 0.f;
#pragma unroll
    for (int i = 0; i < 4; i++)
        sum += __expf(v[i].x - bm) + __expf(v[i].y - bm) + __expf(v[i].z - bm) + __expf(v[i].w - bm);
    smem[tid] = sum; __syncthreads();
    for (int off = 128; off > 0; off >>= 1) {
        if (tid < off) smem[tid] += smem[tid + off];
        __syncthreads();
    }
    if (tid == 0) { g_cmax[b * 32 + c] = bm; g_csum[b * 32 + c] = smem[0]; }
}

/* K7: combine chunk stats. grid 64, 32 thr */
__global__ void __launch_bounds__(32) k_smax_comb() {
    int b = blockIdx.x, t = threadIdx.x;
    float m = g_cmax[b * 32 + t], s = g_csum[b * 32 + t];
    float M = m;
    for (int off = 16; off > 0; off >>= 1) M = fmaxf(M, __shfl_xor_sync(0xffffffffu, M, off));
    float part = s * __expf(m - M);
    for (int off = 16; off > 0; off >>= 1) part += __shfl_xor_sync(0xffffffffu, part, off);
    if (t == 0) { g_rmax[b] = M; g_rsum[b] = part; }
}

/* K8: write soft_full. grid 2048, 256 thr, float4 */
__global__ void __launch_bounds__(256) k_smax_write(float* __restrict__ out) {
    int b = blockIdx.x >> 5, c = blockIdx.x & 31, tid = threadIdx.x;
    const float4* row = (const float4*)(g_sif + (size_t)b * NKEYS + c * 4096);
    float4* orow = (float4*)(out + 2 * BB * K_MAX + (size_t)b * NKEYS + c * 4096);
    float M = g_rmax[b], inv = 1.f / g_rsum[b];
#pragma unroll
    for (int i = 0; i < 4; i++) {
        float4 v = row[tid + 256 * i];
        orow[tid + 256 * i] = make_float4(__expf(v.x - M) * inv, __expf(v.y - M) * inv,
                                          __expf(v.z - M) * inv, __expf(v.w - M) * inv);
    }
}

/* K9: refine + top-64 + alphas. grid 64, 256 thr. Reads exact scores. */
__global__ void __launch_bounds__(256) k_refine(const float* __restrict__ taup,
                                                const float* __restrict__ lamp,
                                                const int* __restrict__ warmp,
                                                float* __restrict__ out) {
    int b = blockIdx.x, tid = threadIdx.x;
    int wid = tid >> 5, lane = tid & 31;
    __shared__ float raw[M_CAND];
    __shared__ float bvw[256];
    __shared__ float wv[8]; __shared__ int wi[8];
    __shared__ int win_i;
    __shared__ float vals[K_MAX];
    __shared__ int   gids[K_MAX];
    __shared__ float sD;
    float tau = taup[0], lam = lamp[0];
    int warm = warmp[0];

    float lsum = 0.f;
    for (int r = 0; r < 16; r++) {
        int i = tid + 256 * r;
        float si = g_refS[b * M_CAND + i];
        float v;
        if (warm) v = si;
        else {
            float g = 1.f / (1.f + expf(-lam * (si - tau)));
            v = g * expf(si);
        }
        raw[i] = v;
        lsum += v;
    }
    bvw[tid] = lsum; __syncthreads();
    for (int off = 128; off > 0; off >>= 1) {
        if (tid < off) bvw[tid] += bvw[tid + off];
        __syncthreads();
    }
    if (tid == 0) sD = bvw[0] + EPSF;
    __syncthreads();
    if (!warm) {
        float invD = 1.f / sD;
        for (int r = 0; r < 16; r++) raw[tid + 256 * r] *= invD;
    }
    __syncthreads();

    float lv = -FLT_MAX; int li = tid;
    for (int r = 0; r < 16; r++) {
        int i = tid + 256 * r;
        float v = raw[i];
        if (v > lv) { lv = v; li = i; }
    }
    for (int rr = 0; rr < K_MAX; rr++) {
        float bv = lv; int bidx = li;
#pragma unroll
        for (int off = 16; off > 0; off >>= 1) {
            float ov = __shfl_xor_sync(0xffffffffu, bv, off);
            int   oi = __shfl_xor_sync(0xffffffffu, bidx, off);
            if (ov > bv || (ov == bv && oi < bidx)) { bv = ov; bidx = oi; }
        }
        if (lane == 0) { wv[wid] = bv; wi[wid] = bidx; }
        __syncthreads();
        if (tid == 0) {
            float gbv = wv[0]; int gbi = wi[0];
            for (int w = 1; w < 8; w++) {
                if (wv[w] > gbv || (wv[w] == gbv && wi[w] < gbi)) { gbv = wv[w]; gbi = wi[w]; }
            }
            win_i = gbi;
            vals[rr] = gbv;
            gids[rr] = g_topc[b * M_TOP + (gbi >> 7)] * NPC + (gbi & 127);
        }
        __syncthreads();
        if ((win_i & 255) == tid) {
            raw[win_i] = -FLT_MAX;
            lv = -FLT_MAX; li = tid;
            for (int r = 0; r < 16; r++) {
                int i = tid + 256 * r;
                float v = raw[i];
                if (v > lv) { lv = v; li = i; }
            }
        }
        __syncthreads();
    }

    if (tid == 0) {
        float alphas[K_MAX];
        if (warm) {
            float m = -FLT_MAX;
            for (int r = 0; r < K_MAX; r++) m = fmaxf(m, vals[r]);
            float ssum = 0.f;
            for (int r = 0; r < K_MAX; r++) { alphas[r] = expf(vals[r] - m); ssum += alphas[r]; }
            float inv = 1.f / ssum;
            for (int r = 0; r < K_MAX; r++) alphas[r] *= inv;
        } else {
            float ssum = 0.f;
            for (int r = 0; r < K_MAX; r++) ssum += vals[r];
            float inv = 1.f / (ssum + EPSF);
            for (int r = 0; r < K_MAX; r++) alphas[r] = vals[r] * inv;
        }
        for (int r = 0; r < K_MAX; r++) {
            out[b * K_MAX + r] = alphas[r];
            out[BB * K_MAX + b * K_MAX + r] = (float)gids[r];
        }
    }
}

extern "C" void kernel_launch(void* const* d_in, const int* in_sizes, int n_in,
                              void* d_out, int out_size) {
    const float* z    = (const float*)d_in[0];
    const float* keys = (const float*)d_in[1];
    const float* WQ   = (const float*)d_in[2];
    const float* aw   = (const float*)d_in[3];
    const float* tau  = (const float*)d_in[4];
    const float* cent = (const float*)d_in[5];
    const float* lam  = (const float*)d_in[6];
    const int*   warm = (const int*)d_in[7];
    float* out = (float*)d_out;

    const size_t mma_smem  = (size_t)(49280 + 8192 + 64) * sizeof(float);  /* 224.8 KB */
    const size_t cent_smem = (size_t)(32768 + 8192 + 64) * sizeof(float);  /* 160.25 KB */
    cudaFuncSetAttribute(k_mma, cudaFuncAttributeMaxDynamicSharedMemorySize, (int)mma_smem);
    cudaFuncSetAttribute(k_centroid, cudaFuncAttributeMaxDynamicSharedMemorySize, (int)cent_smem);

    k_qpart<<<256, 128>>>(WQ, z);                    /* 0 */
    k_qcombine<<<256, 128>>>(aw);                    /* 1 */
    k_centroid<<<64, 512, cent_smem>>>(cent);        /* 2 */
    k_topc<<<64, 512>>>();                           /* 3 */
    k_clmask<<<64, 32>>>();                          /* 4 */
    k_mma<<<NKEYS / DN, 256, mma_smem>>>(keys);      /* 5 <- ncu window */
    k_smax_part<<<2048, 256>>>();
    k_smax_comb<<<64, 32>>>();
    k_smax_write<<<2048, 256>>>(out);
    k_refine<<<64, 256>>>(tau, lam, warm, out);
}